// round 6
// baseline (speedup 1.0000x reference)
#include <cuda_runtime.h>
#include <math.h>
#include <stdint.h>

#define B_    4096
#define T_    16
#define D_    256
#define L_    4
#define KIN_  1056
#define EPS_  1e-4f
#define M_BIG (B_ * T_)          // 65536

// ---------------- scratch ----------------
__device__ float g_tokA[M_BIG * D_];
__device__ float g_tokB[M_BIG * D_];
__device__ float g_states[M_BIG * D_];
__device__ float g_cat[B_ * KIN_];
__device__ float g_part[2][4 * M_BIG];   // per-quarter partial sum-of-squares
__device__ float g_Wi[L_ * D_ * D_];     // rna(W_in  * nw)
__device__ float g_Wo[L_ * D_ * D_];     // rna(W_out)
__device__ float g_Ws[L_ * D_ * D_];     // rna(W_skip * nw)
__device__ float g_W0r[D_ * KIN_];       // rna(W0)

// ---------------- PTX helpers ----------------
__device__ __forceinline__ uint32_t smem_u32(const void* p) {
    uint32_t a;
    asm("{ .reg .u64 t; cvta.to.shared.u64 t, %1; cvt.u32.u64 %0, t; }" : "=r"(a) : "l"(p));
    return a;
}
__device__ __forceinline__ uint32_t f2tf32(float x) {
    uint32_t r; asm("cvt.rna.tf32.f32 %0, %1;" : "=r"(r) : "f"(x)); return r;
}
__device__ __forceinline__ float rna(float x) { return __uint_as_float(f2tf32(x)); }

__device__ __forceinline__ void mma_tf32(float* c, const uint32_t* a, const uint32_t* b) {
    asm volatile(
        "mma.sync.aligned.m16n8k8.row.col.f32.tf32.tf32.f32 "
        "{%0,%1,%2,%3}, {%4,%5,%6,%7}, {%8,%9}, {%0,%1,%2,%3};"
        : "+f"(c[0]), "+f"(c[1]), "+f"(c[2]), "+f"(c[3])
        : "r"(a[0]), "r"(a[1]), "r"(a[2]), "r"(a[3]), "r"(b[0]), "r"(b[1]));
}
__device__ __forceinline__ void ldsm4(uint32_t* r, uint32_t addr) {
    asm volatile("ldmatrix.sync.aligned.m8n8.x4.shared.b16 {%0,%1,%2,%3}, [%4];"
                 : "=r"(r[0]), "=r"(r[1]), "=r"(r[2]), "=r"(r[3]) : "r"(addr));
}
__device__ __forceinline__ void cp16(uint32_t s, const float* g) {
    asm volatile("{ .reg .u64 gp; cvta.to.global.u64 gp, %1;\n\t"
                 "cp.async.cg.shared.global [%0], [gp], 16; }"
                 :: "r"(s), "l"(g) : "memory");
}
__device__ __forceinline__ void cp_commit() { asm volatile("cp.async.commit_group;" ::: "memory"); }
__device__ __forceinline__ void cp_wait0()  { asm volatile("cp.async.wait_group 0;" ::: "memory"); }
__device__ __forceinline__ void cp_wait1()  { asm volatile("cp.async.wait_group 1;" ::: "memory"); }
__device__ __forceinline__ void cp_wait2()  { asm volatile("cp.async.wait_group 2;" ::: "memory"); }

__device__ __forceinline__ float part_scale(const float* pin, int m) {
    float s = pin[m] + pin[M_BIG + m] + pin[2 * M_BIG + m] + pin[3 * M_BIG + m];
    return rsqrtf(s * (1.0f / 256.0f) + EPS_);
}

// stage one A chunk: 128 rows x 32 k via cp.async, pitch 144B
__device__ __forceinline__ void stageA(uint32_t abase, const float* A, int k0) {
    int row = threadIdx.x >> 1, h = threadIdx.x & 1;
    const float* p = A + (size_t)row * 256 + k0 + h * 16;
    uint32_t d = abase + row * 144 + h * 64;
    cp16(d,      p);
    cp16(d + 16, p + 4);
    cp16(d + 32, p + 8);
    cp16(d + 48, p + 12);
}

// =========== GEMM1 + fused scan (persistent W half, BN=128) ===========
// smem: W 128x1040 = 133120 | A 4x18432 = 73728  (Us reuses A area)
#define SM1_TOT (133120 + 73728)
__global__ __launch_bounds__(256, 1)
void k_gemm_scan(const float* __restrict__ P, const float* __restrict__ Wi,
                 const float* __restrict__ bi, const float* __restrict__ ld_,
                 const float* __restrict__ partIn, float* __restrict__ states)
{
    extern __shared__ float smf[];
    uint32_t sm32 = smem_u32(smf);
    const uint32_t wbm = sm32;
    const uint32_t ab  = sm32 + 133120;
    const int tid = threadIdx.x, lane = tid & 31, wid = tid >> 5;
    const int wm = wid & 1, wn = wid >> 1;
    const int gid = lane >> 2, tig = lane & 3;
    const int lr = lane & 7, lb8 = (lane >> 3) & 1, lb16 = (lane >> 4) & 1;
    const int nbase = blockIdx.y * 128;

    // persistent W half load
    {
        int r = tid >> 1, h = tid & 1;
        const float* s = Wi + (size_t)(nbase + r) * 256 + h * 128;
        uint32_t d = wbm + r * 1040 + h * 512;
#pragma unroll
        for (int j = 0; j < 32; j++) cp16(d + j * 16, s + j * 4);
    }
    cp_commit();

    const uint32_t aoff = (uint32_t)(wm * 64 + lr + lb8 * 8) * 144 + lb16 * 16;
    const uint32_t boff = wbm + (uint32_t)(wn * 32 + lr + lb16 * 8) * 1040 + lb8 * 16;

    for (int tile = blockIdx.x; tile < M_BIG / 128; tile += gridDim.x) {
        const int m0 = tile * 128;
        const float* Am = P + (size_t)m0 * 256;

        stageA(ab,             Am, 0);  cp_commit();
        stageA(ab + 18432,     Am, 32); cp_commit();
        stageA(ab + 2 * 18432, Am, 64); cp_commit();

        float acc[4][4][4];
#pragma unroll
        for (int mt = 0; mt < 4; mt++)
#pragma unroll
            for (int j = 0; j < 4; j++)
#pragma unroll
                for (int q = 0; q < 4; q++) acc[mt][j][q] = 0.f;

#pragma unroll 1
        for (int c = 0; c < 8; c++) {
            cp_wait2();
            __syncthreads();
            if (c + 3 < 8) stageA(ab + ((c + 3) & 3) * 18432, Am, (c + 3) * 32);
            cp_commit();
            const uint32_t A0 = ab + (c & 3) * 18432;
#pragma unroll
            for (int ks = 0; ks < 4; ks++) {
                uint32_t a[4][4], bf[2][4];
#pragma unroll
                for (int mt = 0; mt < 4; mt++)
                    ldsm4(a[mt], A0 + aoff + mt * (16 * 144) + ks * 32);
#pragma unroll
                for (int p = 0; p < 2; p++)
                    ldsm4(bf[p], boff + p * (16 * 1040) + (c * 32 + ks * 8) * 4);
#pragma unroll
                for (int mt = 0; mt < 4; mt++) {
                    mma_tf32(acc[mt][0], a[mt], &bf[0][0]);
                    mma_tf32(acc[mt][1], a[mt], &bf[0][2]);
                    mma_tf32(acc[mt][2], a[mt], &bf[1][0]);
                    mma_tf32(acc[mt][3], a[mt], &bf[1][2]);
                }
            }
        }
        __syncthreads();

        // epilogue: u = scale_m * acc + bi -> scan over T=16 -> states
        float* Us = smf + 133120 / 4;   // [128][132]
#pragma unroll
        for (int mt = 0; mt < 4; mt++) {
            int r = wm * 64 + mt * 16 + gid;
            float s0 = part_scale(partIn, m0 + r);
            float s1 = part_scale(partIn, m0 + r + 8);
#pragma unroll
            for (int j = 0; j < 4; j++) {
                int col = wn * 32 + j * 8 + tig * 2;
                float bv0 = bi[nbase + col], bv1 = bi[nbase + col + 1];
                Us[r * 132 + col]           = acc[mt][j][0] * s0 + bv0;
                Us[r * 132 + col + 1]       = acc[mt][j][1] * s0 + bv1;
                Us[(r + 8) * 132 + col]     = acc[mt][j][2] * s1 + bv0;
                Us[(r + 8) * 132 + col + 1] = acc[mt][j][3] * s1 + bv1;
            }
        }
        __syncthreads();
#pragma unroll
        for (int rep = 0; rep < 4; rep++) {
            int task = rep * 256 + tid;
            int bb = task >> 7, cc = task & 127;
            float dec = 1.0f / (1.0f + expf(-ld_[nbase + cc]));
            float st = 0.0f;
#pragma unroll
            for (int t = 0; t < 16; t++) {
                st = dec * st + Us[(bb * 16 + t) * 132 + cc];
                Us[(bb * 16 + t) * 132 + cc] = st;
            }
        }
        __syncthreads();
#pragma unroll
        for (int it = 0; it < 16; it++) {
            int f = it * 256 + tid;
            int row = f >> 5, c4 = (f & 31) * 4;
            float4 v = *(float4*)&Us[row * 132 + c4];
            *(float4*)&states[(size_t)(m0 + row) * 256 + nbase + c4] = v;
        }
        __syncthreads();
    }
}

// =========== GEMM2 (persistent [Ws;Wo] quarter, BN=64, K=512) ===========
// smem: W 64x2064 = 132096 | A 4x18432 = 73728
#define SM2_TOT (132096 + 73728)
__global__ __launch_bounds__(256, 1)
void k_gemm2(const float* __restrict__ P, const float* __restrict__ Wsp,
             const float* __restrict__ states, const float* __restrict__ Wo,
             const float* __restrict__ partIn,
             const float* __restrict__ bo, const float* __restrict__ bsk,
             float* __restrict__ Q, float* __restrict__ partOut)
{
    extern __shared__ float smf[];
    uint32_t sm32 = smem_u32(smf);
    const uint32_t wbm = sm32;
    const uint32_t ab  = sm32 + 132096;
    const int tid = threadIdx.x, lane = tid & 31, wid = tid >> 5;
    const int wm = wid & 3, wn = wid >> 2;
    const int gid = lane >> 2, tig = lane & 3;
    const int lr = lane & 7, lb8 = (lane >> 3) & 1, lb16 = (lane >> 4) & 1;
    const int qb = blockIdx.y * 64;

    // persistent W quarter: k<256 from Wsp, k>=256 from Wo
    {
        int r = tid >> 2, q = tid & 3;
        const float* s = (q < 2) ? (Wsp + (size_t)(qb + r) * 256 + q * 128)
                                 : (Wo  + (size_t)(qb + r) * 256 + (q - 2) * 128);
        uint32_t d = wbm + r * 2064 + q * 512;
#pragma unroll
        for (int j = 0; j < 32; j++) cp16(d + j * 16, s + j * 4);
    }
    cp_commit();

    const uint32_t aoff = (uint32_t)(wm * 32 + lr + lb8 * 8) * 144 + lb16 * 16;
    const uint32_t boff = wbm + (uint32_t)(wn * 32 + lr + lb16 * 8) * 2064 + lb8 * 16;

    for (int tile = blockIdx.x; tile < M_BIG / 128; tile += gridDim.x) {
        const int m0 = tile * 128;
        const float* Pm = P + (size_t)m0 * 256;
        const float* Sm = states + (size_t)m0 * 256;

        stageA(ab,             Pm, 0);  cp_commit();
        stageA(ab + 18432,     Pm, 32); cp_commit();
        stageA(ab + 2 * 18432, Pm, 64); cp_commit();

        float acc[2][4][4];
#pragma unroll
        for (int mt = 0; mt < 2; mt++)
#pragma unroll
            for (int j = 0; j < 4; j++)
#pragma unroll
                for (int q = 0; q < 4; q++) acc[mt][j][q] = 0.f;

#pragma unroll 1
        for (int c = 0; c < 16; c++) {
            cp_wait2();
            __syncthreads();
            if (c + 3 < 16) {
                int cn = c + 3;
                stageA(ab + (cn & 3) * 18432, cn < 8 ? Pm : Sm, (cn & 7) * 32);
            }
            cp_commit();
            if (c == 8) {
                // acc holds x@Ws'; multiply by rmsnorm row scale before Wo pass
#pragma unroll
                for (int mt = 0; mt < 2; mt++) {
                    int r = m0 + wm * 32 + mt * 16 + gid;
                    float s0 = part_scale(partIn, r);
                    float s1 = part_scale(partIn, r + 8);
#pragma unroll
                    for (int j = 0; j < 4; j++) {
                        acc[mt][j][0] *= s0; acc[mt][j][1] *= s0;
                        acc[mt][j][2] *= s1; acc[mt][j][3] *= s1;
                    }
                }
            }
            const uint32_t A0 = ab + (c & 3) * 18432;
#pragma unroll
            for (int ks = 0; ks < 4; ks++) {
                uint32_t a[2][4], bf[2][4];
#pragma unroll
                for (int mt = 0; mt < 2; mt++)
                    ldsm4(a[mt], A0 + aoff + mt * (16 * 144) + ks * 32);
#pragma unroll
                for (int p = 0; p < 2; p++)
                    ldsm4(bf[p], boff + p * (16 * 2064) + (c * 32 + ks * 8) * 4);
#pragma unroll
                for (int mt = 0; mt < 2; mt++) {
                    mma_tf32(acc[mt][0], a[mt], &bf[0][0]);
                    mma_tf32(acc[mt][1], a[mt], &bf[0][2]);
                    mma_tf32(acc[mt][2], a[mt], &bf[1][0]);
                    mma_tf32(acc[mt][3], a[mt], &bf[1][2]);
                }
            }
        }
        __syncthreads();

        // epilogue: Us = P residual, += acc + bo + bsk; write Q; partial sumsq
        float* Us = smf + 132096 / 4;   // [128][68]
#pragma unroll
        for (int it = 0; it < 8; it++) {
            int f = it * 256 + tid;
            int row = f >> 4, c4 = (f & 15) * 4;
            float4 v = *(const float4*)&Pm[(size_t)row * 256 + qb + c4];
            *(float4*)&Us[row * 68 + c4] = v;
        }
        __syncthreads();
#pragma unroll
        for (int mt = 0; mt < 2; mt++) {
            int r = wm * 32 + mt * 16 + gid;
#pragma unroll
            for (int j = 0; j < 4; j++) {
                int col = wn * 32 + j * 8 + tig * 2;
                float bb0 = bo[qb + col]     + bsk[qb + col];
                float bb1 = bo[qb + col + 1] + bsk[qb + col + 1];
                Us[r * 68 + col]           += acc[mt][j][0] + bb0;
                Us[r * 68 + col + 1]       += acc[mt][j][1] + bb1;
                Us[(r + 8) * 68 + col]     += acc[mt][j][2] + bb0;
                Us[(r + 8) * 68 + col + 1] += acc[mt][j][3] + bb1;
            }
        }
        __syncthreads();
#pragma unroll
        for (int it = 0; it < 8; it++) {
            int f = it * 256 + tid;
            int row = f >> 4, c4 = (f & 15) * 4;
            float4 v = *(float4*)&Us[row * 68 + c4];
            *(float4*)&Q[(size_t)(m0 + row) * 256 + qb + c4] = v;
        }
        {
            int row = tid >> 1, h = tid & 1;
            float s = 0.f;
#pragma unroll
            for (int j = 0; j < 32; j++) {
                float v = Us[row * 68 + h * 32 + j];
                s += v * v;
            }
            s += __shfl_xor_sync(0xffffffffu, s, 1);
            if (h == 0) partOut[blockIdx.y * M_BIG + m0 + row] = s;
        }
        __syncthreads();
    }
}

// =========== prologue / small kernels ===========
__global__ void prep_weights(const float* __restrict__ Wi, const float* __restrict__ Wo,
                             const float* __restrict__ Wsk, const float* __restrict__ nw,
                             const float* __restrict__ W0)
{
    int i = blockIdx.x * blockDim.x + threadIdx.x;
    if (i < L_ * D_ * D_) {
        int l = i >> 16, k = i & 255;
        float w = nw[l * D_ + k];
        g_Wi[i] = rna(Wi[i] * w);
        g_Ws[i] = rna(Wsk[i] * w);
        g_Wo[i] = rna(Wo[i]);
    }
    if (i < D_ * KIN_) g_W0r[i] = rna(W0[i]);
}

__global__ void shift_scale_kernel(const float* __restrict__ deter,
                                   float* __restrict__ tok, float* __restrict__ part0)
{
    int gw = (blockIdx.x * blockDim.x + threadIdx.x) >> 5;
    if (gw >= B_ * 15) return;
    int lane = threadIdx.x & 31;
    int b = gw / 15, t = gw - b * 15;
    const float4* src = (const float4*)(deter + (size_t)b * 4096 + (t + 1) * 256) + lane;
    float4* dst = (float4*)(tok + (size_t)b * 4096 + t * 256) + lane;
    float4 v0 = src[0], v1 = src[32];
    dst[0] = v0; dst[32] = v1;
    float s = v0.x*v0.x + v0.y*v0.y + v0.z*v0.z + v0.w*v0.w
            + v1.x*v1.x + v1.y*v1.y + v1.z*v1.z + v1.w*v1.w;
#pragma unroll
    for (int o = 16; o > 0; o >>= 1) s += __shfl_xor_sync(0xffffffffu, s, o);
    if (lane == 0) {
        int mm = b * 16 + t;
        part0[mm] = s;
        part0[M_BIG + mm] = 0.f;
        part0[2 * M_BIG + mm] = 0.f;
        part0[3 * M_BIG + mm] = 0.f;
    }
}

__global__ void concat_kernel(const float* __restrict__ stoch,
                              const float* __restrict__ action,
                              float* __restrict__ cat)
{
    int idx = blockIdx.x * blockDim.x + threadIdx.x;
    if (idx >= B_ * KIN_) return;
    int b = idx / KIN_;
    int k = idx - b * KIN_;
    float v;
    if (k < 1024) v = stoch[(size_t)b * 1024 + k];
    else {
        float a = action[(size_t)b * 32 + (k - 1024)];
        v = a / fmaxf(fabsf(a), 1.0f);
    }
    cat[idx] = v;
}

__global__ void apply_norm_kernel(const float* __restrict__ in, const float* __restrict__ w,
                                  float* __restrict__ out)
{
    int gw = (blockIdx.x * blockDim.x + threadIdx.x) >> 5;
    int lane = threadIdx.x & 31;
    const float* rp = in + (size_t)gw * 256 + lane * 8;
    float v[8];
    *(float4*)&v[0] = *(const float4*)rp;
    *(float4*)&v[4] = *(const float4*)(rp + 4);
    float s = 0.f;
#pragma unroll
    for (int j = 0; j < 8; j++) s += v[j] * v[j];
#pragma unroll
    for (int o = 16; o > 0; o >>= 1) s += __shfl_xor_sync(0xffffffffu, s, o);
    float sc = rsqrtf(s * (1.0f / 256.0f) + EPS_);
    float wl[8];
    *(float4*)&wl[0] = *(const float4*)(w + lane * 8);
    *(float4*)&wl[4] = *(const float4*)(w + lane * 8 + 4);
    float o8[8];
#pragma unroll
    for (int j = 0; j < 8; j++) o8[j] = v[j] * sc * wl[j];
    float* op = out + (size_t)gw * 256 + lane * 8;
    *(float4*)op = *(float4*)&o8[0];
    *(float4*)(op + 4) = *(float4*)&o8[4];
}

// =========== input proj (round-5 structure, BM=64) ===========
#define SM_A0   0
#define SM_A1   9216
#define SM_B0   18432
#define SM_B1   55296
#define SM_TOT  92160

__device__ __forceinline__ void stage_chunk_p(float* smf, uint32_t sm32, int buf,
                                              const float* A, const float* W, int k0)
{
    const int tid = threadIdx.x;
    {
        int row = tid >> 2, kc = (tid & 3) * 8;
        const float* p = A + (size_t)row * KIN_ + k0 + kc;
        uint32_t d = sm32 + (buf ? SM_A1 : SM_A0) + row * 144 + kc * 4;
        cp16(d, p); cp16(d + 16, p + 4);
    }
    {
        const float* p = W + (size_t)tid * KIN_ + k0;
        uint32_t d = sm32 + (buf ? SM_B1 : SM_B0) + tid * 144;
#pragma unroll
        for (int j = 0; j < 8; j++) cp16(d + j * 16, p + j * 4);
    }
}

__global__ __launch_bounds__(256, 2)
void k_proj(const float* __restrict__ cat, const float* __restrict__ b0,
            const float* __restrict__ g0, float* __restrict__ tokA,
            float* __restrict__ part0)
{
    extern __shared__ float smf[];
    uint32_t sm32 = smem_u32(smf);
    const int tid = threadIdx.x, wid = tid >> 5, lane = tid & 31;
    const int wm = wid & 1, wn = wid >> 1;
    const int gid = lane >> 2, tig = lane & 3;
    const int lr = lane & 7, lb8 = (lane >> 3) & 1, lb16 = (lane >> 4) & 1;
    const int m0 = blockIdx.x * 64;
    const float* A = cat + (size_t)m0 * KIN_;

    const uint32_t aoff0 = (uint32_t)(wm * 32 + lr + lb8 * 8) * 144 + lb16 * 16;
    const uint32_t aoff1 = aoff0 + 16 * 144;
    const uint32_t boff  = (uint32_t)(wn * 64 + lr + lb16 * 8) * 144 + lb8 * 16;

    float acc[2][8][4];
#pragma unroll
    for (int mt = 0; mt < 2; mt++)
#pragma unroll
        for (int j = 0; j < 8; j++)
#pragma unroll
            for (int q = 0; q < 4; q++) acc[mt][j][q] = 0.f;

    stage_chunk_p(smf, sm32, 0, A, g_W0r, 0);
    cp_commit();
#pragma unroll 1
    for (int i = 0; i < 33; i++) {
        const int b = i & 1;
        if (i + 1 < 33) {
            stage_chunk_p(smf, sm32, (i + 1) & 1, A, g_W0r, (i + 1) * 32);
            cp_commit();
            cp_wait1();
        } else cp_wait0();
        __syncthreads();
        const uint32_t sA = sm32 + (b ? SM_A1 : SM_A0);
        const uint32_t sB = sm32 + (b ? SM_B1 : SM_B0);
#pragma unroll
        for (int ks = 0; ks < 4; ks++) {
            uint32_t a0[4], a1[4], bf[4][4];
            ldsm4(a0, sA + aoff0 + ks * 32);
            ldsm4(a1, sA + aoff1 + ks * 32);
#pragma unroll
            for (int pr = 0; pr < 4; pr++)
                ldsm4(bf[pr], sB + boff + pr * 2304 + ks * 32);
#pragma unroll
            for (int pr = 0; pr < 4; pr++) {
                mma_tf32(acc[0][2*pr],   a0, &bf[pr][0]);
                mma_tf32(acc[0][2*pr+1], a0, &bf[pr][2]);
                mma_tf32(acc[1][2*pr],   a1, &bf[pr][0]);
                mma_tf32(acc[1][2*pr+1], a1, &bf[pr][2]);
            }
        }
        __syncthreads();
    }

    float* Us = smf;   // [64][260]
#pragma unroll
    for (int mt = 0; mt < 2; mt++) {
        int r = wm * 32 + mt * 16 + gid;
#pragma unroll
        for (int j = 0; j < 8; j++) {
            int col = wn * 64 + j * 8 + tig * 2;
            Us[r * 260 + col]           = acc[mt][j][0];
            Us[r * 260 + col + 1]       = acc[mt][j][1];
            Us[(r + 8) * 260 + col]     = acc[mt][j][2];
            Us[(r + 8) * 260 + col + 1] = acc[mt][j][3];
        }
    }
    __syncthreads();
#pragma unroll
    for (int k = 0; k < 8; k++) {
        int row = k * 8 + wid;
        int m = m0 + row;
        float v[8]; float sum = 0.f;
#pragma unroll
        for (int j = 0; j < 8; j++) {
            int c = lane + 32 * j;
            v[j] = Us[row * 260 + c] + b0[c];
            sum += v[j] * v[j];
        }
#pragma unroll
        for (int o = 16; o > 0; o >>= 1) sum += __shfl_xor_sync(0xffffffffu, sum, o);
        float sc = rsqrtf(sum * (1.0f / 256.0f) + EPS_);
        float s2 = 0.f;
#pragma unroll
        for (int j = 0; j < 8; j++) {
            int c = lane + 32 * j;
            float y = v[j] * sc * g0[c];
            y = y / (1.0f + expf(-y));
            s2 += y * y;
            tokA[(size_t)m * 4096 + 3840 + c] = y;
        }
#pragma unroll
        for (int o = 16; o > 0; o >>= 1) s2 += __shfl_xor_sync(0xffffffffu, s2, o);
        if (lane == 0) {
            int mm = m * 16 + 15;
            part0[mm] = s2;
            part0[M_BIG + mm] = 0.f;
            part0[2 * M_BIG + mm] = 0.f;
            part0[3 * M_BIG + mm] = 0.f;
        }
    }
}

// ---------------- launch ----------------
extern "C" void kernel_launch(void* const* d_in, const int* in_sizes, int n_in,
                              void* d_out, int out_size)
{
    const float* stoch      = (const float*)d_in[0];
    const float* deter      = (const float*)d_in[1];
    const float* action     = (const float*)d_in[2];
    const float* W0         = (const float*)d_in[3];
    const float* b0         = (const float*)d_in[4];
    const float* g0         = (const float*)d_in[5];
    const float* norm_w     = (const float*)d_in[6];
    const float* W_in       = (const float*)d_in[7];
    const float* b_in       = (const float*)d_in[8];
    const float* W_out      = (const float*)d_in[9];
    const float* b_out      = (const float*)d_in[10];
    const float* W_skip     = (const float*)d_in[11];
    const float* b_skip     = (const float*)d_in[12];
    const float* log_decay  = (const float*)d_in[13];
    const float* out_norm_w = (const float*)d_in[14];
    float* out = (float*)d_out;

    float *tokA, *tokB, *states, *cat, *part, *Wi_s, *Wo_s, *Ws_s;
    cudaGetSymbolAddress((void**)&tokA,   g_tokA);
    cudaGetSymbolAddress((void**)&tokB,   g_tokB);
    cudaGetSymbolAddress((void**)&states, g_states);
    cudaGetSymbolAddress((void**)&cat,    g_cat);
    cudaGetSymbolAddress((void**)&part,   g_part);
    cudaGetSymbolAddress((void**)&Wi_s,   g_Wi);
    cudaGetSymbolAddress((void**)&Wo_s,   g_Wo);
    cudaGetSymbolAddress((void**)&Ws_s,   g_Ws);

    cudaFuncSetAttribute(k_proj,      cudaFuncAttributeMaxDynamicSharedMemorySize, SM_TOT);
    cudaFuncSetAttribute(k_gemm_scan, cudaFuncAttributeMaxDynamicSharedMemorySize, SM1_TOT);
    cudaFuncSetAttribute(k_gemm2,     cudaFuncAttributeMaxDynamicSharedMemorySize, SM2_TOT);

    prep_weights<<<(D_ * KIN_ + 255) / 256 + 1, 256>>>(W_in, W_out, W_skip, norm_w, W0);
    shift_scale_kernel<<<B_ * 15 / 8, 256>>>(deter, tokA, part);
    concat_kernel<<<(B_ * KIN_ + 255) / 256, 256>>>(stoch, action, cat);
    k_proj<<<B_ / 64, 256, SM_TOT>>>(cat, b0, g0, tokA, part);

    float* Pb = tokA;
    float* Qb = tokB;
    for (int l = 0; l < L_; l++) {
        const float* Wi  = Wi_s + (size_t)l * D_ * D_;
        const float* Wo  = Wo_s + (size_t)l * D_ * D_;
        const float* Ws  = Ws_s + (size_t)l * D_ * D_;
        const float* bi  = b_in      + (size_t)l * D_;
        const float* bo  = b_out     + (size_t)l * D_;
        const float* bsk = b_skip    + (size_t)l * D_;
        const float* ld  = log_decay + (size_t)l * D_;
        float* partIn  = part + (size_t)(l & 1) * 4 * M_BIG;
        float* partOut = part + (size_t)((l + 1) & 1) * 4 * M_BIG;

        k_gemm_scan<<<dim3(148, 2), 256, SM1_TOT>>>(Pb, Wi, bi, ld, partIn, states);
        k_gemm2<<<dim3(148, 4), 256, SM2_TOT>>>(Pb, Ws, states, Wo, partIn,
                                                bo, bsk, Qb, partOut);
        float* tmp = Pb; Pb = Qb; Qb = tmp;
    }

    apply_norm_kernel<<<M_BIG / 8, 256>>>(Pb, out_norm_w, out);
}

// round 7
// speedup vs baseline: 1.1913x; 1.1913x over previous
#include <cuda_runtime.h>
#include <math.h>
#include <stdint.h>

#define B_    4096
#define T_    16
#define D_    256
#define L_    4
#define KIN_  1056
#define EPS_  1e-4f
#define M_BIG (B_ * T_)          // 65536

// ---------------- scratch ----------------
__device__ float g_tokA[M_BIG * D_];
__device__ float g_tokB[M_BIG * D_];
__device__ float g_states[M_BIG * D_];
__device__ float g_cat[B_ * KIN_];
__device__ float g_part[2][4 * M_BIG];   // per-quarter partial sum-of-squares
__device__ float g_Wi[L_ * D_ * D_];     // rna(W_in  * nw)
__device__ float g_Wo[L_ * D_ * D_];     // rna(W_out)
__device__ float g_Ws[L_ * D_ * D_];     // rna(W_skip * nw)
__device__ float g_W0r[D_ * KIN_];       // rna(W0)

// ---------------- PTX helpers ----------------
__device__ __forceinline__ uint32_t smem_u32(const void* p) {
    uint32_t a;
    asm("{ .reg .u64 t; cvta.to.shared.u64 t, %1; cvt.u32.u64 %0, t; }" : "=r"(a) : "l"(p));
    return a;
}
__device__ __forceinline__ uint32_t f2tf32(float x) {
    uint32_t r; asm("cvt.rna.tf32.f32 %0, %1;" : "=r"(r) : "f"(x)); return r;
}
__device__ __forceinline__ float rna(float x) { return __uint_as_float(f2tf32(x)); }

__device__ __forceinline__ void mma_tf32(float* c, const uint32_t* a, const uint32_t* b) {
    asm volatile(
        "mma.sync.aligned.m16n8k8.row.col.f32.tf32.tf32.f32 "
        "{%0,%1,%2,%3}, {%4,%5,%6,%7}, {%8,%9}, {%0,%1,%2,%3};"
        : "+f"(c[0]), "+f"(c[1]), "+f"(c[2]), "+f"(c[3])
        : "r"(a[0]), "r"(a[1]), "r"(a[2]), "r"(a[3]), "r"(b[0]), "r"(b[1]));
}
__device__ __forceinline__ void ldsm4(uint32_t* r, uint32_t addr) {
    asm volatile("ldmatrix.sync.aligned.m8n8.x4.shared.b16 {%0,%1,%2,%3}, [%4];"
                 : "=r"(r[0]), "=r"(r[1]), "=r"(r[2]), "=r"(r[3]) : "r"(addr));
}
__device__ __forceinline__ void cp16(uint32_t s, const float* g) {
    asm volatile("{ .reg .u64 gp; cvta.to.global.u64 gp, %1;\n\t"
                 "cp.async.cg.shared.global [%0], [gp], 16; }"
                 :: "r"(s), "l"(g) : "memory");
}
__device__ __forceinline__ void cp_commit() { asm volatile("cp.async.commit_group;" ::: "memory"); }
__device__ __forceinline__ void cp_wait0()  { asm volatile("cp.async.wait_group 0;" ::: "memory"); }
__device__ __forceinline__ void cp_wait1()  { asm volatile("cp.async.wait_group 1;" ::: "memory"); }
__device__ __forceinline__ void cp_wait2()  { asm volatile("cp.async.wait_group 2;" ::: "memory"); }

__device__ __forceinline__ float part_scale(const float* pin, int m) {
    float s = pin[m] + pin[M_BIG + m] + pin[2 * M_BIG + m] + pin[3 * M_BIG + m];
    return rsqrtf(s * (1.0f / 256.0f) + EPS_);
}

// per-warp A staging: 32 rows x 32 k, pitch 144B; lane = row
__device__ __forceinline__ void stageA_warp(uint32_t dst, const float* Arows, int k0) {
    int lane = threadIdx.x & 31;
    const float* p = Arows + (size_t)lane * 256 + k0;
    uint32_t d = dst + lane * 144;
#pragma unroll
    for (int j = 0; j < 8; j++) cp16(d + j * 16, p + j * 4);
}

#define ACHUNK 4608              // 32*144

// =========== GEMM1 + fused scan: barrier-free, per-warp m32 x n64 ===========
// smem: W 64x1040 = 66560 | A: 8 warps x 3 bufs x 4608 = 110592
#define G1_WB   66560
#define SM1_TOT (G1_WB + 8 * 3 * ACHUNK)    // 177152
__global__ __launch_bounds__(256, 1)
void k_gemm_scan(const float* __restrict__ P, const float* __restrict__ Wi,
                 const float* __restrict__ bi, const float* __restrict__ ld_,
                 const float* __restrict__ partIn, float* __restrict__ states)
{
    extern __shared__ float smf[];
    uint32_t sm32 = smem_u32(smf);
    const int tid = threadIdx.x, lane = tid & 31, w = tid >> 5;
    const int lr = lane & 7, lb8 = (lane >> 3) & 1, lb16 = (lane >> 4) & 1;
    const int gid = lane >> 2, tig = lane & 3;
    const int qb = blockIdx.y * 64;

    // cooperative persistent W-quarter load (once)
    {
        int r = tid >> 2, q = tid & 3;
        const float* s = Wi + (size_t)(qb + r) * 256 + q * 64;
        uint32_t d = sm32 + r * 1040 + q * 256;
#pragma unroll
        for (int j = 0; j < 16; j++) cp16(d + j * 16, s + j * 4);
    }
    cp_commit(); cp_wait0();
    __syncthreads();          // the ONLY block-wide barrier

    const uint32_t AB = sm32 + G1_WB + w * (3 * ACHUNK);
    float* ABf = smf + (G1_WB / 4) + w * (3 * ACHUNK / 4);

    for (int tile = blockIdx.x; tile < M_BIG / 256; tile += gridDim.x) {
        const int m0w = tile * 256 + w * 32;
        const float* Am = P + (size_t)m0w * 256;

        stageA_warp(AB,              Am, 0);  cp_commit();
        stageA_warp(AB + ACHUNK,     Am, 32); cp_commit();
        stageA_warp(AB + 2 * ACHUNK, Am, 64); cp_commit();

        float acc[2][8][4];
#pragma unroll
        for (int mt = 0; mt < 2; mt++)
#pragma unroll
            for (int j = 0; j < 8; j++)
#pragma unroll
                for (int q = 0; q < 4; q++) acc[mt][j][q] = 0.f;

#pragma unroll 1
        for (int c = 0; c < 8; c++) {
            cp_wait2();
            __syncwarp();
            const uint32_t A0 = AB + (c % 3) * ACHUNK;
#pragma unroll
            for (int ks = 0; ks < 4; ks++) {
                uint32_t a[2][4];
                ldsm4(a[0], A0 + (lr + lb8 * 8) * 144 + lb16 * 16 + ks * 32);
                ldsm4(a[1], A0 + (16 + lr + lb8 * 8) * 144 + lb16 * 16 + ks * 32);
#pragma unroll
                for (int ng = 0; ng < 4; ng++) {
                    uint32_t bf[4];
                    ldsm4(bf, sm32 + (ng * 16 + lr + lb16 * 8) * 1040 + lb8 * 16
                              + (c * 32 + ks * 8) * 4);
                    mma_tf32(acc[0][ng * 2],     a[0], &bf[0]);
                    mma_tf32(acc[0][ng * 2 + 1], a[0], &bf[2]);
                    mma_tf32(acc[1][ng * 2],     a[1], &bf[0]);
                    mma_tf32(acc[1][ng * 2 + 1], a[1], &bf[2]);
                }
            }
            if (c + 3 < 8) stageA_warp(AB + ((c + 3) % 3) * ACHUNK, Am, (c + 3) * 32);
            cp_commit();
        }
        __syncwarp();

        // per-warp epilogue: Us[32][64] in own A region, sc[32] after it
        float* Us = ABf;
        float* sc = ABf + 2048;
#pragma unroll
        for (int mt = 0; mt < 2; mt++) {
            int r = mt * 16 + gid;
#pragma unroll
            for (int j = 0; j < 8; j++) {
                int col = j * 8 + tig * 2;
                Us[r * 64 + col]           = acc[mt][j][0];
                Us[r * 64 + col + 1]       = acc[mt][j][1];
                Us[(r + 8) * 64 + col]     = acc[mt][j][2];
                Us[(r + 8) * 64 + col + 1] = acc[mt][j][3];
            }
        }
        sc[lane] = part_scale(partIn, m0w + lane);
        __syncwarp();
        // scan along t within the warp's 2 batches x 64 cols
#pragma unroll
        for (int q = 0; q < 4; q++) {
            int task = lane + 32 * q;
            int bb = task >> 6, cc = task & 63;
            float dec = 1.0f / (1.0f + expf(-ld_[qb + cc]));
            float bias = bi[qb + cc];
            float st = 0.f;
#pragma unroll
            for (int tt = 0; tt < 16; tt++) {
                int row = bb * 16 + tt;
                float u = Us[row * 64 + cc] * sc[row] + bias;
                st = dec * st + u;
                Us[row * 64 + cc] = st;
            }
        }
        __syncwarp();
#pragma unroll
        for (int i = 0; i < 16; i++) {
            int f = lane + 32 * i;
            int row = f >> 4, c4 = (f & 15) * 4;
            float4 v = *(float4*)&Us[row * 64 + c4];
            *(float4*)&states[(size_t)(m0w + row) * 256 + qb + c4] = v;
        }
        __syncwarp();
    }
}

// =========== GEMM2: barrier-free, per-warp m32 x n64, K=512 ([Ws;Wo]) ===========
// smem: W 64x2064 = 132096 | A: 8 warps x 2 bufs x 4608 = 73728
#define G2_WB   132096
#define SM2_TOT (G2_WB + 8 * 2 * ACHUNK)    // 205824
__global__ __launch_bounds__(256, 1)
void k_gemm2(const float* __restrict__ P, const float* __restrict__ Wsp,
             const float* __restrict__ states, const float* __restrict__ Wo,
             const float* __restrict__ partIn,
             const float* __restrict__ bo, const float* __restrict__ bsk,
             float* __restrict__ Q, float* __restrict__ partOut)
{
    extern __shared__ float smf[];
    uint32_t sm32 = smem_u32(smf);
    const int tid = threadIdx.x, lane = tid & 31, w = tid >> 5;
    const int lr = lane & 7, lb8 = (lane >> 3) & 1, lb16 = (lane >> 4) & 1;
    const int gid = lane >> 2, tig = lane & 3;
    const int qb = blockIdx.y * 64;

    // persistent [Ws | Wo] quarter: row r holds Ws'[qb+r][0:256] then Wo[qb+r][0:256]
    {
        int r = tid >> 2, q = tid & 3;
        const float* s = (q < 2) ? (Wsp + (size_t)(qb + r) * 256 + q * 128)
                                 : (Wo  + (size_t)(qb + r) * 256 + (q - 2) * 128);
        uint32_t d = sm32 + r * 2064 + q * 512;
#pragma unroll
        for (int j = 0; j < 32; j++) cp16(d + j * 16, s + j * 4);
    }
    cp_commit(); cp_wait0();
    __syncthreads();

    const uint32_t AB = sm32 + G2_WB + w * (2 * ACHUNK);
    float* ABf = smf + (G2_WB / 4) + w * (2 * ACHUNK / 4);

    for (int tile = blockIdx.x; tile < M_BIG / 256; tile += gridDim.x) {
        const int m0w = tile * 256 + w * 32;
        const float* Pm = P + (size_t)m0w * 256;
        const float* Sm = states + (size_t)m0w * 256;

        stageA_warp(AB,          Pm, 0);  cp_commit();
        stageA_warp(AB + ACHUNK, Pm, 32); cp_commit();

        float acc[2][8][4];
#pragma unroll
        for (int mt = 0; mt < 2; mt++)
#pragma unroll
            for (int j = 0; j < 8; j++)
#pragma unroll
                for (int q = 0; q < 4; q++) acc[mt][j][q] = 0.f;

#pragma unroll 1
        for (int c = 0; c < 16; c++) {
            cp_wait1();
            __syncwarp();
            if (c == 8) {
                // finished x@Ws' pass: apply rmsnorm row scales
#pragma unroll
                for (int mt = 0; mt < 2; mt++) {
                    float s0 = part_scale(partIn, m0w + mt * 16 + gid);
                    float s1 = part_scale(partIn, m0w + mt * 16 + gid + 8);
#pragma unroll
                    for (int j = 0; j < 8; j++) {
                        acc[mt][j][0] *= s0; acc[mt][j][1] *= s0;
                        acc[mt][j][2] *= s1; acc[mt][j][3] *= s1;
                    }
                }
            }
            const uint32_t A0 = AB + (c & 1) * ACHUNK;
#pragma unroll
            for (int ks = 0; ks < 4; ks++) {
                uint32_t a[2][4];
                ldsm4(a[0], A0 + (lr + lb8 * 8) * 144 + lb16 * 16 + ks * 32);
                ldsm4(a[1], A0 + (16 + lr + lb8 * 8) * 144 + lb16 * 16 + ks * 32);
#pragma unroll
                for (int ng = 0; ng < 4; ng++) {
                    uint32_t bf[4];
                    ldsm4(bf, sm32 + (ng * 16 + lr + lb16 * 8) * 2064 + lb8 * 16
                              + (c * 32 + ks * 8) * 4);
                    mma_tf32(acc[0][ng * 2],     a[0], &bf[0]);
                    mma_tf32(acc[0][ng * 2 + 1], a[0], &bf[2]);
                    mma_tf32(acc[1][ng * 2],     a[1], &bf[0]);
                    mma_tf32(acc[1][ng * 2 + 1], a[1], &bf[2]);
                }
            }
            if (c + 2 < 16) {
                int cn = c + 2;
                stageA_warp(AB + (cn & 1) * ACHUNK, cn < 8 ? Pm : Sm, (cn & 7) * 32);
            }
            cp_commit();
        }
        __syncwarp();

        // per-warp epilogue: Us[32][64]; add biases at STS
        float* Us = ABf;
#pragma unroll
        for (int mt = 0; mt < 2; mt++) {
            int r = mt * 16 + gid;
#pragma unroll
            for (int j = 0; j < 8; j++) {
                int col = j * 8 + tig * 2;
                float bb0 = bo[qb + col]     + bsk[qb + col];
                float bb1 = bo[qb + col + 1] + bsk[qb + col + 1];
                Us[r * 64 + col]           = acc[mt][j][0] + bb0;
                Us[r * 64 + col + 1]       = acc[mt][j][1] + bb1;
                Us[(r + 8) * 64 + col]     = acc[mt][j][2] + bb0;
                Us[(r + 8) * 64 + col + 1] = acc[mt][j][3] + bb1;
            }
        }
        __syncwarp();
        // residual + store + per-row partial sumsq over this n-quarter
#pragma unroll
        for (int i = 0; i < 16; i++) {
            int f = lane + 32 * i;
            int row = f >> 4, c4 = (f & 15) * 4;
            float4 v = *(float4*)&Us[row * 64 + c4];
            float4 p = *(const float4*)&Pm[(size_t)row * 256 + qb + c4];
            v.x += p.x; v.y += p.y; v.z += p.z; v.w += p.w;
            *(float4*)&Q[(size_t)(m0w + row) * 256 + qb + c4] = v;
            float s = v.x * v.x + v.y * v.y + v.z * v.z + v.w * v.w;
            s += __shfl_xor_sync(0xffffffffu, s, 1);
            s += __shfl_xor_sync(0xffffffffu, s, 2);
            s += __shfl_xor_sync(0xffffffffu, s, 4);
            s += __shfl_xor_sync(0xffffffffu, s, 8);
            if ((lane & 15) == 0)
                partOut[(size_t)blockIdx.y * M_BIG + m0w + row] = s;
        }
        __syncwarp();
    }
}

// =========== prologue / small kernels ===========
__global__ void prep_weights(const float* __restrict__ Wi, const float* __restrict__ Wo,
                             const float* __restrict__ Wsk, const float* __restrict__ nw,
                             const float* __restrict__ W0)
{
    int i = blockIdx.x * blockDim.x + threadIdx.x;
    if (i < L_ * D_ * D_) {
        int l = i >> 16, k = i & 255;
        float w = nw[l * D_ + k];
        g_Wi[i] = rna(Wi[i] * w);
        g_Ws[i] = rna(Wsk[i] * w);
        g_Wo[i] = rna(Wo[i]);
    }
    if (i < D_ * KIN_) g_W0r[i] = rna(W0[i]);
}

__global__ void shift_scale_kernel(const float* __restrict__ deter,
                                   float* __restrict__ tok, float* __restrict__ part0)
{
    int gw = (blockIdx.x * blockDim.x + threadIdx.x) >> 5;
    if (gw >= B_ * 15) return;
    int lane = threadIdx.x & 31;
    int b = gw / 15, t = gw - b * 15;
    const float4* src = (const float4*)(deter + (size_t)b * 4096 + (t + 1) * 256) + lane;
    float4* dst = (float4*)(tok + (size_t)b * 4096 + t * 256) + lane;
    float4 v0 = src[0], v1 = src[32];
    dst[0] = v0; dst[32] = v1;
    float s = v0.x*v0.x + v0.y*v0.y + v0.z*v0.z + v0.w*v0.w
            + v1.x*v1.x + v1.y*v1.y + v1.z*v1.z + v1.w*v1.w;
#pragma unroll
    for (int o = 16; o > 0; o >>= 1) s += __shfl_xor_sync(0xffffffffu, s, o);
    if (lane == 0) {
        int mm = b * 16 + t;
        part0[mm] = s;
        part0[M_BIG + mm] = 0.f;
        part0[2 * M_BIG + mm] = 0.f;
        part0[3 * M_BIG + mm] = 0.f;
    }
}

__global__ void concat_kernel(const float* __restrict__ stoch,
                              const float* __restrict__ action,
                              float* __restrict__ cat)
{
    int idx = blockIdx.x * blockDim.x + threadIdx.x;
    if (idx >= B_ * KIN_) return;
    int b = idx / KIN_;
    int k = idx - b * KIN_;
    float v;
    if (k < 1024) v = stoch[(size_t)b * 1024 + k];
    else {
        float a = action[(size_t)b * 32 + (k - 1024)];
        v = a / fmaxf(fabsf(a), 1.0f);
    }
    cat[idx] = v;
}

__global__ void apply_norm_kernel(const float* __restrict__ in, const float* __restrict__ w,
                                  float* __restrict__ out)
{
    int gw = (blockIdx.x * blockDim.x + threadIdx.x) >> 5;
    int lane = threadIdx.x & 31;
    const float* rp = in + (size_t)gw * 256 + lane * 8;
    float v[8];
    *(float4*)&v[0] = *(const float4*)rp;
    *(float4*)&v[4] = *(const float4*)(rp + 4);
    float s = 0.f;
#pragma unroll
    for (int j = 0; j < 8; j++) s += v[j] * v[j];
#pragma unroll
    for (int o = 16; o > 0; o >>= 1) s += __shfl_xor_sync(0xffffffffu, s, o);
    float sc = rsqrtf(s * (1.0f / 256.0f) + EPS_);
    float wl[8];
    *(float4*)&wl[0] = *(const float4*)(w + lane * 8);
    *(float4*)&wl[4] = *(const float4*)(w + lane * 8 + 4);
    float o8[8];
#pragma unroll
    for (int j = 0; j < 8; j++) o8[j] = v[j] * sc * wl[j];
    float* op = out + (size_t)gw * 256 + lane * 8;
    *(float4*)op = *(float4*)&o8[0];
    *(float4*)(op + 4) = *(float4*)&o8[4];
}

// =========== input proj (round-6 structure, BM=64) ===========
#define SM_A0   0
#define SM_A1   9216
#define SM_B0   18432
#define SM_B1   55296
#define SM_TOT  92160

__device__ __forceinline__ void stage_chunk_p(float* smf, uint32_t sm32, int buf,
                                              const float* A, const float* W, int k0)
{
    const int tid = threadIdx.x;
    {
        int row = tid >> 2, kc = (tid & 3) * 8;
        const float* p = A + (size_t)row * KIN_ + k0 + kc;
        uint32_t d = sm32 + (buf ? SM_A1 : SM_A0) + row * 144 + kc * 4;
        cp16(d, p); cp16(d + 16, p + 4);
    }
    {
        const float* p = W + (size_t)tid * KIN_ + k0;
        uint32_t d = sm32 + (buf ? SM_B1 : SM_B0) + tid * 144;
#pragma unroll
        for (int j = 0; j < 8; j++) cp16(d + j * 16, p + j * 4);
    }
}

__global__ __launch_bounds__(256, 2)
void k_proj(const float* __restrict__ cat, const float* __restrict__ b0,
            const float* __restrict__ g0, float* __restrict__ tokA,
            float* __restrict__ part0)
{
    extern __shared__ float smf[];
    uint32_t sm32 = smem_u32(smf);
    const int tid = threadIdx.x, wid = tid >> 5, lane = tid & 31;
    const int wm = wid & 1, wn = wid >> 1;
    const int gid = lane >> 2, tig = lane & 3;
    const int lr = lane & 7, lb8 = (lane >> 3) & 1, lb16 = (lane >> 4) & 1;
    const int m0 = blockIdx.x * 64;
    const float* A = cat + (size_t)m0 * KIN_;

    const uint32_t aoff0 = (uint32_t)(wm * 32 + lr + lb8 * 8) * 144 + lb16 * 16;
    const uint32_t aoff1 = aoff0 + 16 * 144;
    const uint32_t boff  = (uint32_t)(wn * 64 + lr + lb16 * 8) * 144 + lb8 * 16;

    float acc[2][8][4];
#pragma unroll
    for (int mt = 0; mt < 2; mt++)
#pragma unroll
        for (int j = 0; j < 8; j++)
#pragma unroll
            for (int q = 0; q < 4; q++) acc[mt][j][q] = 0.f;

    stage_chunk_p(smf, sm32, 0, A, g_W0r, 0);
    cp_commit();
#pragma unroll 1
    for (int i = 0; i < 33; i++) {
        const int b = i & 1;
        if (i + 1 < 33) {
            stage_chunk_p(smf, sm32, (i + 1) & 1, A, g_W0r, (i + 1) * 32);
            cp_commit();
            cp_wait1();
        } else cp_wait0();
        __syncthreads();
        const uint32_t sA = sm32 + (b ? SM_A1 : SM_A0);
        const uint32_t sB = sm32 + (b ? SM_B1 : SM_B0);
#pragma unroll
        for (int ks = 0; ks < 4; ks++) {
            uint32_t a0[4], a1[4], bf[4][4];
            ldsm4(a0, sA + aoff0 + ks * 32);
            ldsm4(a1, sA + aoff1 + ks * 32);
#pragma unroll
            for (int pr = 0; pr < 4; pr++)
                ldsm4(bf[pr], sB + boff + pr * 2304 + ks * 32);
#pragma unroll
            for (int pr = 0; pr < 4; pr++) {
                mma_tf32(acc[0][2*pr],   a0, &bf[pr][0]);
                mma_tf32(acc[0][2*pr+1], a0, &bf[pr][2]);
                mma_tf32(acc[1][2*pr],   a1, &bf[pr][0]);
                mma_tf32(acc[1][2*pr+1], a1, &bf[pr][2]);
            }
        }
        __syncthreads();
    }

    float* Us = smf;   // [64][260]
#pragma unroll
    for (int mt = 0; mt < 2; mt++) {
        int r = wm * 32 + mt * 16 + gid;
#pragma unroll
        for (int j = 0; j < 8; j++) {
            int col = wn * 64 + j * 8 + tig * 2;
            Us[r * 260 + col]           = acc[mt][j][0];
            Us[r * 260 + col + 1]       = acc[mt][j][1];
            Us[(r + 8) * 260 + col]     = acc[mt][j][2];
            Us[(r + 8) * 260 + col + 1] = acc[mt][j][3];
        }
    }
    __syncthreads();
#pragma unroll
    for (int k = 0; k < 8; k++) {
        int row = k * 8 + wid;
        int m = m0 + row;
        float v[8]; float sum = 0.f;
#pragma unroll
        for (int j = 0; j < 8; j++) {
            int c = lane + 32 * j;
            v[j] = Us[row * 260 + c] + b0[c];
            sum += v[j] * v[j];
        }
#pragma unroll
        for (int o = 16; o > 0; o >>= 1) sum += __shfl_xor_sync(0xffffffffu, sum, o);
        float sc = rsqrtf(sum * (1.0f / 256.0f) + EPS_);
        float s2 = 0.f;
#pragma unroll
        for (int j = 0; j < 8; j++) {
            int c = lane + 32 * j;
            float y = v[j] * sc * g0[c];
            y = y / (1.0f + expf(-y));
            s2 += y * y;
            tokA[(size_t)m * 4096 + 3840 + c] = y;
        }
#pragma unroll
        for (int o = 16; o > 0; o >>= 1) s2 += __shfl_xor_sync(0xffffffffu, s2, o);
        if (lane == 0) {
            int mm = m * 16 + 15;
            part0[mm] = s2;
            part0[M_BIG + mm] = 0.f;
            part0[2 * M_BIG + mm] = 0.f;
            part0[3 * M_BIG + mm] = 0.f;
        }
    }
}

// ---------------- launch ----------------
extern "C" void kernel_launch(void* const* d_in, const int* in_sizes, int n_in,
                              void* d_out, int out_size)
{
    const float* stoch      = (const float*)d_in[0];
    const float* deter      = (const float*)d_in[1];
    const float* action     = (const float*)d_in[2];
    const float* W0         = (const float*)d_in[3];
    const float* b0         = (const float*)d_in[4];
    const float* g0         = (const float*)d_in[5];
    const float* norm_w     = (const float*)d_in[6];
    const float* W_in       = (const float*)d_in[7];
    const float* b_in       = (const float*)d_in[8];
    const float* W_out      = (const float*)d_in[9];
    const float* b_out      = (const float*)d_in[10];
    const float* W_skip     = (const float*)d_in[11];
    const float* b_skip     = (const float*)d_in[12];
    const float* log_decay  = (const float*)d_in[13];
    const float* out_norm_w = (const float*)d_in[14];
    float* out = (float*)d_out;

    float *tokA, *tokB, *states, *cat, *part, *Wi_s, *Wo_s, *Ws_s;
    cudaGetSymbolAddress((void**)&tokA,   g_tokA);
    cudaGetSymbolAddress((void**)&tokB,   g_tokB);
    cudaGetSymbolAddress((void**)&states, g_states);
    cudaGetSymbolAddress((void**)&cat,    g_cat);
    cudaGetSymbolAddress((void**)&part,   g_part);
    cudaGetSymbolAddress((void**)&Wi_s,   g_Wi);
    cudaGetSymbolAddress((void**)&Wo_s,   g_Wo);
    cudaGetSymbolAddress((void**)&Ws_s,   g_Ws);

    cudaFuncSetAttribute(k_proj,      cudaFuncAttributeMaxDynamicSharedMemorySize, SM_TOT);
    cudaFuncSetAttribute(k_gemm_scan, cudaFuncAttributeMaxDynamicSharedMemorySize, SM1_TOT);
    cudaFuncSetAttribute(k_gemm2,     cudaFuncAttributeMaxDynamicSharedMemorySize, SM2_TOT);

    prep_weights<<<(D_ * KIN_ + 255) / 256 + 1, 256>>>(W_in, W_out, W_skip, norm_w, W0);
    shift_scale_kernel<<<B_ * 15 / 8, 256>>>(deter, tokA, part);
    concat_kernel<<<(B_ * KIN_ + 255) / 256, 256>>>(stoch, action, cat);
    k_proj<<<B_ / 64, 256, SM_TOT>>>(cat, b0, g0, tokA, part);

    float* Pb = tokA;
    float* Qb = tokB;
    for (int l = 0; l < L_; l++) {
        const float* Wi  = Wi_s + (size_t)l * D_ * D_;
        const float* Wo  = Wo_s + (size_t)l * D_ * D_;
        const float* Ws  = Ws_s + (size_t)l * D_ * D_;
        const float* bi  = b_in      + (size_t)l * D_;
        const float* bo  = b_out     + (size_t)l * D_;
        const float* bsk = b_skip    + (size_t)l * D_;
        const float* ld  = log_decay + (size_t)l * D_;
        float* partIn  = part + (size_t)(l & 1) * 4 * M_BIG;
        float* partOut = part + (size_t)((l + 1) & 1) * 4 * M_BIG;

        k_gemm_scan<<<dim3(37, 4), 256, SM1_TOT>>>(Pb, Wi, bi, ld, partIn, states);
        k_gemm2<<<dim3(37, 4), 256, SM2_TOT>>>(Pb, Ws, states, Wo, partIn,
                                               bo, bsk, Qb, partOut);
        float* tmp = Pb; Pb = Qb; Qb = tmp;
    }

    apply_norm_kernel<<<M_BIG / 8, 256>>>(Pb, out_norm_w, out);
}

// round 9
// speedup vs baseline: 1.3245x; 1.1118x over previous
#include <cuda_runtime.h>
#include <math.h>
#include <stdint.h>

#define B_    4096
#define T_    16
#define D_    256
#define L_    4
#define KIN_  1056
#define EPS_  1e-4f
#define M_BIG (B_ * T_)          // 65536

// ---------------- scratch ----------------
__device__ float g_tokA[M_BIG * D_];
__device__ float g_tokB[M_BIG * D_];
__device__ float g_states[M_BIG * D_];
__device__ float g_cat[B_ * KIN_];
__device__ float g_part[2][4 * M_BIG];   // per-quarter partial sum-of-squares
__device__ float g_Wi[L_ * D_ * D_];     // rna(W_in  * nw)
__device__ float g_Wo[L_ * D_ * D_];     // rna(W_out)
__device__ float g_Ws[L_ * D_ * D_];     // rna(W_skip * nw)
__device__ float g_W0r[D_ * KIN_];       // rna(W0)

// ---------------- PTX helpers ----------------
__device__ __forceinline__ uint32_t smem_u32(const void* p) {
    uint32_t a;
    asm("{ .reg .u64 t; cvta.to.shared.u64 t, %1; cvt.u32.u64 %0, t; }" : "=r"(a) : "l"(p));
    return a;
}
__device__ __forceinline__ uint32_t f2tf32(float x) {
    uint32_t r; asm("cvt.rna.tf32.f32 %0, %1;" : "=r"(r) : "f"(x)); return r;
}
__device__ __forceinline__ float rna(float x) { return __uint_as_float(f2tf32(x)); }

__device__ __forceinline__ void mma_tf32(float* c, const uint32_t* a, const uint32_t* b) {
    asm volatile(
        "mma.sync.aligned.m16n8k8.row.col.f32.tf32.tf32.f32 "
        "{%0,%1,%2,%3}, {%4,%5,%6,%7}, {%8,%9}, {%0,%1,%2,%3};"
        : "+f"(c[0]), "+f"(c[1]), "+f"(c[2]), "+f"(c[3])
        : "r"(a[0]), "r"(a[1]), "r"(a[2]), "r"(a[3]), "r"(b[0]), "r"(b[1]));
}
__device__ __forceinline__ void ldsm4(uint32_t* r, uint32_t addr) {
    asm volatile("ldmatrix.sync.aligned.m8n8.x4.shared.b16 {%0,%1,%2,%3}, [%4];"
                 : "=r"(r[0]), "=r"(r[1]), "=r"(r[2]), "=r"(r[3]) : "r"(addr));
}
__device__ __forceinline__ void cp16(uint32_t s, const float* g) {
    asm volatile("{ .reg .u64 gp; cvta.to.global.u64 gp, %1;\n\t"
                 "cp.async.cg.shared.global [%0], [gp], 16; }"
                 :: "r"(s), "l"(g) : "memory");
}
__device__ __forceinline__ void cp_commit() { asm volatile("cp.async.commit_group;" ::: "memory"); }
__device__ __forceinline__ void cp_wait0()  { asm volatile("cp.async.wait_group 0;" ::: "memory"); }
__device__ __forceinline__ void cp_wait2()  { asm volatile("cp.async.wait_group 2;" ::: "memory"); }
__device__ __forceinline__ void cp_wait1()  { asm volatile("cp.async.wait_group 1;" ::: "memory"); }
#define BARP(id) asm volatile("bar.sync %0, 64;" :: "r"(id) : "memory")

__device__ __forceinline__ float part_scale(const float* pin, int m) {
    float s = pin[m] + pin[M_BIG + m] + pin[2 * M_BIG + m] + pin[3 * M_BIG + m];
    return rsqrtf(s * (1.0f / 256.0f) + EPS_);
}

#define ACHUNK 4608              // 32*144

// pair-shared A staging: 32 rows x 32 k; each warp of the pair stages 16 rows
__device__ __forceinline__ void stage_pair(uint32_t dst, const float* Agrp, int k0, int nh) {
    int lane = threadIdx.x & 31;
    int row  = nh * 16 + (lane >> 1);
    int part = lane & 1;
    const float* p = Agrp + (size_t)row * 256 + k0 + part * 16;
    uint32_t d = dst + row * 144 + part * 64;
    cp16(d,      p);
    cp16(d + 16, p + 4);
    cp16(d + 32, p + 8);
    cp16(d + 48, p + 12);
}

// =========== GEMM1 + fused scan: pair-shared, BN=128, 4 A bufs ===========
// smem: W 128x1040B = 133120 | 4 groups x 18432 (4 A bufs / epilogue Us+sc)
#define G1_WB    133120
#define G1_REG   18432
#define SM1_TOT  (G1_WB + 4 * G1_REG)      // 206848
__global__ __launch_bounds__(256, 1)
void k_gemm_scan(const float* __restrict__ P, const float* __restrict__ Wi,
                 const float* __restrict__ bi, const float* __restrict__ ld_,
                 const float* __restrict__ partIn, float* __restrict__ states)
{
    extern __shared__ float smf[];
    uint32_t sm32 = smem_u32(smf);
    const int tid = threadIdx.x, lane = tid & 31, w = tid >> 5;
    const int grp = w >> 1, nh = w & 1, bid = grp + 1;
    const int lr = lane & 7, lb8 = (lane >> 3) & 1, lb16 = (lane >> 4) & 1;
    const int gid = lane >> 2, tig = lane & 3;
    const int qb = blockIdx.y * 128;

    // persistent W (128 n-rows x 256 k)
    {
        int r = tid >> 1, h = tid & 1;
        const float* s = Wi + (size_t)(qb + r) * 256 + h * 128;
        uint32_t d = sm32 + r * 1040 + h * 512;
#pragma unroll
        for (int j = 0; j < 32; j++) cp16(d + j * 16, s + j * 4);
    }
    cp_commit(); cp_wait0();
    __syncthreads();

    const uint32_t AB = sm32 + G1_WB + grp * G1_REG;
    float* ABf = smf + (G1_WB / 4) + grp * (G1_REG / 4);

    for (int tile = blockIdx.x; tile < M_BIG / 128; tile += gridDim.x) {
        const int m0g = tile * 128 + grp * 32;
        const float* Am = P + (size_t)m0g * 256;

        stage_pair(AB,              Am, 0,  nh); cp_commit();
        stage_pair(AB + ACHUNK,     Am, 32, nh); cp_commit();
        stage_pair(AB + 2 * ACHUNK, Am, 64, nh); cp_commit();

        float acc[2][8][4];
#pragma unroll
        for (int mt = 0; mt < 2; mt++)
#pragma unroll
            for (int j = 0; j < 8; j++)
#pragma unroll
                for (int q = 0; q < 4; q++) acc[mt][j][q] = 0.f;

#pragma unroll 1
        for (int c = 0; c < 8; c++) {
            cp_wait2();
            BARP(bid);                         // pair: chunk c staged (both halves),
                                               // partner finished iter c-1 reads
            const uint32_t A0 = AB + (c & 3) * ACHUNK;
#pragma unroll
            for (int ks = 0; ks < 4; ks++) {
                uint32_t a[2][4];
                ldsm4(a[0], A0 + (lr + lb8 * 8) * 144 + lb16 * 16 + ks * 32);
                ldsm4(a[1], A0 + (16 + lr + lb8 * 8) * 144 + lb16 * 16 + ks * 32);
#pragma unroll
                for (int ng = 0; ng < 4; ng++) {
                    uint32_t bf[4];
                    ldsm4(bf, sm32 + (nh * 64 + ng * 16 + lr + lb16 * 8) * 1040
                              + lb8 * 16 + (c * 32 + ks * 8) * 4);
                    mma_tf32(acc[0][ng * 2],     a[0], &bf[0]);
                    mma_tf32(acc[0][ng * 2 + 1], a[0], &bf[2]);
                    mma_tf32(acc[1][ng * 2],     a[1], &bf[0]);
                    mma_tf32(acc[1][ng * 2 + 1], a[1], &bf[2]);
                }
            }
            // stage into buf (c+3)&3: last read at iter c-1; BARP above makes it safe
            if (c + 3 < 8) stage_pair(AB + ((c + 3) & 3) * ACHUNK, Am, (c + 3) * 32, nh);
            cp_commit();
        }
        BARP(bid);   // pair done reading all A bufs before Us overwrites region

        // epilogue: Us[32][128] per group; sc[32] after it
        float* Us = ABf;
        float* sc = ABf + 4096;
#pragma unroll
        for (int mt = 0; mt < 2; mt++) {
            int r = mt * 16 + gid;
#pragma unroll
            for (int j = 0; j < 8; j++) {
                int col = nh * 64 + j * 8 + tig * 2;
                Us[r * 128 + col]           = acc[mt][j][0];
                Us[r * 128 + col + 1]       = acc[mt][j][1];
                Us[(r + 8) * 128 + col]     = acc[mt][j][2];
                Us[(r + 8) * 128 + col + 1] = acc[mt][j][3];
            }
        }
        if (nh == 0) sc[lane] = part_scale(partIn, m0g + lane);
        BARP(bid);
        // scan along t: 2 batches x 128 cols = 256 chains / 64 lanes
#pragma unroll
        for (int q = 0; q < 4; q++) {
            int task = nh * 32 + lane + 64 * q;
            int bb = task >> 7, cc = task & 127;
            float dec = 1.0f / (1.0f + expf(-ld_[qb + cc]));
            float bias = bi[qb + cc];
            float st = 0.f;
#pragma unroll
            for (int tt = 0; tt < 16; tt++) {
                int row = bb * 16 + tt;
                float u = Us[row * 128 + cc] * sc[row] + bias;
                st = dec * st + u;
                Us[row * 128 + cc] = st;
            }
        }
        BARP(bid);
#pragma unroll
        for (int i = 0; i < 16; i++) {
            int f = nh * 32 + lane + 64 * i;
            int row = f >> 5, c4 = (f & 31) * 4;
            float4 v = *(float4*)&Us[row * 128 + c4];
            *(float4*)&states[(size_t)(m0g + row) * 256 + qb + c4] = v;
        }
        BARP(bid);
    }
}

// =========== GEMM2: pair-shared, BN=64, K=512 ([Ws;Wo]), 4 A bufs ===========
// smem: W 64x2064B = 132096 | 4 groups x 18432
#define G2_WB    132096
#define G2_REG   18432
#define SM2_TOT  (G2_WB + 4 * G2_REG)      // 205824
__global__ __launch_bounds__(256, 1)
void k_gemm2(const float* __restrict__ P, const float* __restrict__ Wsp,
             const float* __restrict__ states, const float* __restrict__ Wo,
             const float* __restrict__ partIn,
             const float* __restrict__ bo, const float* __restrict__ bsk,
             float* __restrict__ Q, float* __restrict__ partOut)
{
    extern __shared__ float smf[];
    uint32_t sm32 = smem_u32(smf);
    const int tid = threadIdx.x, lane = tid & 31, w = tid >> 5;
    const int grp = w >> 1, nh = w & 1, bid = grp + 1;
    const int lr = lane & 7, lb8 = (lane >> 3) & 1, lb16 = (lane >> 4) & 1;
    const int gid = lane >> 2, tig = lane & 3;
    const int qb = blockIdx.y * 64;

    // persistent [Ws | Wo] quarter (64 n-rows x 512 k)
    {
        int r = tid >> 2, q = tid & 3;
        const float* s = (q < 2) ? (Wsp + (size_t)(qb + r) * 256 + q * 128)
                                 : (Wo  + (size_t)(qb + r) * 256 + (q - 2) * 128);
        uint32_t d = sm32 + r * 2064 + q * 512;
#pragma unroll
        for (int j = 0; j < 32; j++) cp16(d + j * 16, s + j * 4);
    }
    cp_commit(); cp_wait0();
    __syncthreads();

    const uint32_t AB = sm32 + G2_WB + grp * G2_REG;
    float* ABf = smf + (G2_WB / 4) + grp * (G2_REG / 4);

    for (int tile = blockIdx.x; tile < M_BIG / 128; tile += gridDim.x) {
        const int m0g = tile * 128 + grp * 32;
        const float* Pm = P + (size_t)m0g * 256;
        const float* Sm = states + (size_t)m0g * 256;

        stage_pair(AB,              Pm, 0,  nh); cp_commit();
        stage_pair(AB + ACHUNK,     Pm, 32, nh); cp_commit();
        stage_pair(AB + 2 * ACHUNK, Pm, 64, nh); cp_commit();

        float acc[2][4][4];
#pragma unroll
        for (int mt = 0; mt < 2; mt++)
#pragma unroll
            for (int j = 0; j < 4; j++)
#pragma unroll
                for (int q = 0; q < 4; q++) acc[mt][j][q] = 0.f;

#pragma unroll 1
        for (int c = 0; c < 16; c++) {
            cp_wait2();
            BARP(bid);
            if (c == 8) {
                // finished x@Ws' half: apply rmsnorm row scales to acc
#pragma unroll
                for (int mt = 0; mt < 2; mt++) {
                    float s0 = part_scale(partIn, m0g + mt * 16 + gid);
                    float s1 = part_scale(partIn, m0g + mt * 16 + gid + 8);
#pragma unroll
                    for (int j = 0; j < 4; j++) {
                        acc[mt][j][0] *= s0; acc[mt][j][1] *= s0;
                        acc[mt][j][2] *= s1; acc[mt][j][3] *= s1;
                    }
                }
            }
            const uint32_t A0 = AB + (c & 3) * ACHUNK;
#pragma unroll
            for (int ks = 0; ks < 4; ks++) {
                uint32_t a[2][4];
                ldsm4(a[0], A0 + (lr + lb8 * 8) * 144 + lb16 * 16 + ks * 32);
                ldsm4(a[1], A0 + (16 + lr + lb8 * 8) * 144 + lb16 * 16 + ks * 32);
#pragma unroll
                for (int ng = 0; ng < 2; ng++) {
                    uint32_t bf[4];
                    ldsm4(bf, sm32 + (nh * 32 + ng * 16 + lr + lb16 * 8) * 2064
                              + lb8 * 16 + (c * 32 + ks * 8) * 4);
                    mma_tf32(acc[0][ng * 2],     a[0], &bf[0]);
                    mma_tf32(acc[0][ng * 2 + 1], a[0], &bf[2]);
                    mma_tf32(acc[1][ng * 2],     a[1], &bf[0]);
                    mma_tf32(acc[1][ng * 2 + 1], a[1], &bf[2]);
                }
            }
            if (c + 3 < 16) {
                int cn = c + 3;
                stage_pair(AB + (cn & 3) * ACHUNK, cn < 8 ? Pm : Sm, (cn & 7) * 32, nh);
            }
            cp_commit();
        }
        BARP(bid);

        // epilogue: Us[32][64] per group; biases at STS
        float* Us = ABf;
#pragma unroll
        for (int mt = 0; mt < 2; mt++) {
            int r = mt * 16 + gid;
#pragma unroll
            for (int j = 0; j < 4; j++) {
                int col = nh * 32 + j * 8 + tig * 2;
                float bb0 = bo[qb + col]     + bsk[qb + col];
                float bb1 = bo[qb + col + 1] + bsk[qb + col + 1];
                Us[r * 64 + col]           = acc[mt][j][0] + bb0;
                Us[r * 64 + col + 1]       = acc[mt][j][1] + bb1;
                Us[(r + 8) * 64 + col]     = acc[mt][j][2] + bb0;
                Us[(r + 8) * 64 + col + 1] = acc[mt][j][3] + bb1;
            }
        }
        BARP(bid);
        // residual + store + per-row partial sumsq over the group's n64
#pragma unroll
        for (int i = 0; i < 8; i++) {
            int f = nh * 32 + lane + 64 * i;
            int row = f >> 4, c4 = (f & 15) * 4;
            float4 v = *(float4*)&Us[row * 64 + c4];
            float4 p = *(const float4*)&Pm[(size_t)row * 256 + qb + c4];
            v.x += p.x; v.y += p.y; v.z += p.z; v.w += p.w;
            *(float4*)&Q[(size_t)(m0g + row) * 256 + qb + c4] = v;
            float s = v.x * v.x + v.y * v.y + v.z * v.z + v.w * v.w;
            s += __shfl_xor_sync(0xffffffffu, s, 1);
            s += __shfl_xor_sync(0xffffffffu, s, 2);
            s += __shfl_xor_sync(0xffffffffu, s, 4);
            s += __shfl_xor_sync(0xffffffffu, s, 8);
            if ((lane & 15) == 0)
                partOut[(size_t)blockIdx.y * M_BIG + m0g + row] = s;
        }
        BARP(bid);
    }
}

// =========== prologue / small kernels ===========
__global__ void prep_weights(const float* __restrict__ Wi, const float* __restrict__ Wo,
                             const float* __restrict__ Wsk, const float* __restrict__ nw,
                             const float* __restrict__ W0)
{
    int i = blockIdx.x * blockDim.x + threadIdx.x;
    if (i < L_ * D_ * D_) {
        int l = i >> 16, k = i & 255;
        float w = nw[l * D_ + k];
        g_Wi[i] = rna(Wi[i] * w);
        g_Ws[i] = rna(Wsk[i] * w);
        g_Wo[i] = rna(Wo[i]);
    }
    if (i < D_ * KIN_) g_W0r[i] = rna(W0[i]);
}

__global__ void shift_scale_kernel(const float* __restrict__ deter,
                                   float* __restrict__ tok, float* __restrict__ part0)
{
    int gw = (blockIdx.x * blockDim.x + threadIdx.x) >> 5;
    if (gw >= B_ * 15) return;
    int lane = threadIdx.x & 31;
    int b = gw / 15, t = gw - b * 15;
    const float4* src = (const float4*)(deter + (size_t)b * 4096 + (t + 1) * 256) + lane;
    float4* dst = (float4*)(tok + (size_t)b * 4096 + t * 256) + lane;
    float4 v0 = src[0], v1 = src[32];
    dst[0] = v0; dst[32] = v1;
    float s = v0.x*v0.x + v0.y*v0.y + v0.z*v0.z + v0.w*v0.w
            + v1.x*v1.x + v1.y*v1.y + v1.z*v1.z + v1.w*v1.w;
#pragma unroll
    for (int o = 16; o > 0; o >>= 1) s += __shfl_xor_sync(0xffffffffu, s, o);
    if (lane == 0) {
        int mm = b * 16 + t;
        part0[mm] = s;
        part0[M_BIG + mm] = 0.f;
        part0[2 * M_BIG + mm] = 0.f;
        part0[3 * M_BIG + mm] = 0.f;
    }
}

__global__ void concat_kernel(const float* __restrict__ stoch,
                              const float* __restrict__ action,
                              float* __restrict__ cat)
{
    int idx = blockIdx.x * blockDim.x + threadIdx.x;
    if (idx >= B_ * KIN_) return;
    int b = idx / KIN_;
    int k = idx - b * KIN_;
    float v;
    if (k < 1024) v = stoch[(size_t)b * 1024 + k];
    else {
        float a = action[(size_t)b * 32 + (k - 1024)];
        v = a / fmaxf(fabsf(a), 1.0f);
    }
    cat[idx] = v;
}

__global__ void apply_norm_kernel(const float* __restrict__ in, const float* __restrict__ w,
                                  float* __restrict__ out)
{
    int gw = (blockIdx.x * blockDim.x + threadIdx.x) >> 5;
    int lane = threadIdx.x & 31;
    const float* rp = in + (size_t)gw * 256 + lane * 8;
    float v[8];
    *(float4*)&v[0] = *(const float4*)rp;
    *(float4*)&v[4] = *(const float4*)(rp + 4);
    float s = 0.f;
#pragma unroll
    for (int j = 0; j < 8; j++) s += v[j] * v[j];
#pragma unroll
    for (int o = 16; o > 0; o >>= 1) s += __shfl_xor_sync(0xffffffffu, s, o);
    float sc = rsqrtf(s * (1.0f / 256.0f) + EPS_);
    float wl[8];
    *(float4*)&wl[0] = *(const float4*)(w + lane * 8);
    *(float4*)&wl[4] = *(const float4*)(w + lane * 8 + 4);
    float o8[8];
#pragma unroll
    for (int j = 0; j < 8; j++) o8[j] = v[j] * sc * wl[j];
    float* op = out + (size_t)gw * 256 + lane * 8;
    *(float4*)op = *(float4*)&o8[0];
    *(float4*)(op + 4) = *(float4*)&o8[4];
}

// =========== input proj: BM=32, 128 CTAs ===========
#define SMP_A0   0
#define SMP_A1   4608
#define SMP_B0   9216
#define SMP_B1   46080
#define SMP_TOT  82944

__device__ __forceinline__ void stage_chunk_p(uint32_t sm32, int buf,
                                              const float* A, const float* W, int k0)
{
    const int tid = threadIdx.x;
    {
        int row = tid >> 3, kc = (tid & 7) * 4;
        const float* p = A + (size_t)row * KIN_ + k0 + kc;
        uint32_t d = sm32 + (buf ? SMP_A1 : SMP_A0) + row * 144 + kc * 4;
        cp16(d, p);
    }
    {
        const float* p = W + (size_t)tid * KIN_ + k0;
        uint32_t d = sm32 + (buf ? SMP_B1 : SMP_B0) + tid * 144;
#pragma unroll
        for (int j = 0; j < 8; j++) cp16(d + j * 16, p + j * 4);
    }
}

__global__ __launch_bounds__(256, 2)
void k_proj(const float* __restrict__ cat, const float* __restrict__ b0,
            const float* __restrict__ g0, float* __restrict__ tokA,
            float* __restrict__ part0)
{
    extern __shared__ float smf[];
    uint32_t sm32 = smem_u32(smf);
    const int tid = threadIdx.x, wid = tid >> 5, lane = tid & 31;
    const int wm = wid & 1, wn = wid >> 1;
    const int gid = lane >> 2, tig = lane & 3;
    const int lr = lane & 7, lb8 = (lane >> 3) & 1, lb16 = (lane >> 4) & 1;
    const int m0 = blockIdx.x * 32;
    const float* A = cat + (size_t)m0 * KIN_;

    const uint32_t aoff = (uint32_t)(wm * 16 + lr + lb8 * 8) * 144 + lb16 * 16;
    const uint32_t boff = (uint32_t)(wn * 64 + lr + lb16 * 8) * 144 + lb8 * 16;

    float acc[8][4];
#pragma unroll
    for (int j = 0; j < 8; j++)
#pragma unroll
        for (int q = 0; q < 4; q++) acc[j][q] = 0.f;

    stage_chunk_p(sm32, 0, A, g_W0r, 0);
    cp_commit();
#pragma unroll 1
    for (int i = 0; i < 33; i++) {
        const int b = i & 1;
        if (i + 1 < 33) {
            stage_chunk_p(sm32, (i + 1) & 1, A, g_W0r, (i + 1) * 32);
            cp_commit();
            cp_wait1();
        } else cp_wait0();
        __syncthreads();
        const uint32_t sA = sm32 + (b ? SMP_A1 : SMP_A0);
        const uint32_t sB = sm32 + (b ? SMP_B1 : SMP_B0);
#pragma unroll
        for (int ks = 0; ks < 4; ks++) {
            uint32_t a0[4], bf[4][4];
            ldsm4(a0, sA + aoff + ks * 32);
#pragma unroll
            for (int pr = 0; pr < 4; pr++)
                ldsm4(bf[pr], sB + boff + pr * 2304 + ks * 32);
#pragma unroll
            for (int pr = 0; pr < 4; pr++) {
                mma_tf32(acc[2*pr],   a0, &bf[pr][0]);
                mma_tf32(acc[2*pr+1], a0, &bf[pr][2]);
            }
        }
        __syncthreads();
    }

    float* Us = smf;   // [32][260]
#pragma unroll
    for (int j = 0; j < 8; j++) {
        int r = wm * 16 + gid;
        int col = wn * 64 + j * 8 + tig * 2;
        Us[r * 260 + col]           = acc[j][0];
        Us[r * 260 + col + 1]       = acc[j][1];
        Us[(r + 8) * 260 + col]     = acc[j][2];
        Us[(r + 8) * 260 + col + 1] = acc[j][3];
    }
    __syncthreads();
#pragma unroll
    for (int k = 0; k < 4; k++) {
        int row = k * 8 + wid;
        int m = m0 + row;
        float v[8]; float sum = 0.f;
#pragma unroll
        for (int j = 0; j < 8; j++) {
            int c = lane + 32 * j;
            v[j] = Us[row * 260 + c] + b0[c];
            sum += v[j] * v[j];
        }
#pragma unroll
        for (int o = 16; o > 0; o >>= 1) sum += __shfl_xor_sync(0xffffffffu, sum, o);
        float sc = rsqrtf(sum * (1.0f / 256.0f) + EPS_);
        float s2 = 0.f;
#pragma unroll
        for (int j = 0; j < 8; j++) {
            int c = lane + 32 * j;
            float y = v[j] * sc * g0[c];
            y = y / (1.0f + expf(-y));
            s2 += y * y;
            tokA[(size_t)m * 4096 + 3840 + c] = y;
        }
#pragma unroll
        for (int o = 16; o > 0; o >>= 1) s2 += __shfl_xor_sync(0xffffffffu, s2, o);
        if (lane == 0) {
            int mm = m * 16 + 15;
            part0[mm] = s2;
            part0[M_BIG + mm] = 0.f;
            part0[2 * M_BIG + mm] = 0.f;
            part0[3 * M_BIG + mm] = 0.f;
        }
    }
}

// ---------------- launch ----------------
extern "C" void kernel_launch(void* const* d_in, const int* in_sizes, int n_in,
                              void* d_out, int out_size)
{
    const float* stoch      = (const float*)d_in[0];
    const float* deter      = (const float*)d_in[1];
    const float* action     = (const float*)d_in[2];
    const float* W0         = (const float*)d_in[3];
    const float* b0         = (const float*)d_in[4];
    const float* g0         = (const float*)d_in[5];
    const float* norm_w     = (const float*)d_in[6];
    const float* W_in       = (const float*)d_in[7];
    const float* b_in       = (const float*)d_in[8];
    const float* W_out      = (const float*)d_in[9];
    const float* b_out      = (const float*)d_in[10];
    const float* W_skip     = (const float*)d_in[11];
    const float* b_skip     = (const float*)d_in[12];
    const float* log_decay  = (const float*)d_in[13];
    const float* out_norm_w = (const float*)d_in[14];
    float* out = (float*)d_out;

    float *tokA, *tokB, *states, *cat, *part, *Wi_s, *Wo_s, *Ws_s;
    cudaGetSymbolAddress((void**)&tokA,   g_tokA);
    cudaGetSymbolAddress((void**)&tokB,   g_tokB);
    cudaGetSymbolAddress((void**)&states, g_states);
    cudaGetSymbolAddress((void**)&cat,    g_cat);
    cudaGetSymbolAddress((void**)&part,   g_part);
    cudaGetSymbolAddress((void**)&Wi_s,   g_Wi);
    cudaGetSymbolAddress((void**)&Wo_s,   g_Wo);
    cudaGetSymbolAddress((void**)&Ws_s,   g_Ws);

    cudaFuncSetAttribute(k_proj,      cudaFuncAttributeMaxDynamicSharedMemorySize, SMP_TOT);
    cudaFuncSetAttribute(k_gemm_scan, cudaFuncAttributeMaxDynamicSharedMemorySize, SM1_TOT);
    cudaFuncSetAttribute(k_gemm2,     cudaFuncAttributeMaxDynamicSharedMemorySize, SM2_TOT);

    prep_weights<<<(D_ * KIN_ + 255) / 256 + 1, 256>>>(W_in, W_out, W_skip, norm_w, W0);
    shift_scale_kernel<<<B_ * 15 / 8, 256>>>(deter, tokA, part);
    concat_kernel<<<(B_ * KIN_ + 255) / 256, 256>>>(stoch, action, cat);
    k_proj<<<B_ / 32, 256, SMP_TOT>>>(cat, b0, g0, tokA, part);

    float* Pb = tokA;
    float* Qb = tokB;
    for (int l = 0; l < L_; l++) {
        const float* Wi  = Wi_s + (size_t)l * D_ * D_;
        const float* Wo  = Wo_s + (size_t)l * D_ * D_;
        const float* Ws  = Ws_s + (size_t)l * D_ * D_;
        const float* bi  = b_in      + (size_t)l * D_;
        const float* bo  = b_out     + (size_t)l * D_;
        const float* bsk = b_skip    + (size_t)l * D_;
        const float* ld  = log_decay + (size_t)l * D_;
        float* partIn  = part + (size_t)(l & 1) * 4 * M_BIG;
        float* partOut = part + (size_t)((l + 1) & 1) * 4 * M_BIG;

        k_gemm_scan<<<dim3(74, 2), 256, SM1_TOT>>>(Pb, Wi, bi, ld, partIn, states);
        k_gemm2<<<dim3(37, 4), 256, SM2_TOT>>>(Pb, Ws, states, Wo, partIn,
                                               bo, bsk, Qb, partOut);
        float* tmp = Pb; Pb = Qb; Qb = tmp;
    }

    apply_norm_kernel<<<M_BIG / 8, 256>>>(Pb, out_norm_w, out);
}

// round 10
// speedup vs baseline: 1.4364x; 1.0845x over previous
#include <cuda_runtime.h>
#include <math.h>
#include <stdint.h>

#define B_    4096
#define T_    16
#define D_    256
#define L_    4
#define KIN_  1056
#define EPS_  1e-4f
#define M_BIG (B_ * T_)          // 65536

// ---------------- scratch ----------------
__device__ float g_tokA[M_BIG * D_];
__device__ float g_tokB[M_BIG * D_];
__device__ float g_states[M_BIG * D_];
__device__ float g_cat[B_ * KIN_];
__device__ float g_part[2][4 * M_BIG];   // per-quarter partial sum-of-squares
__device__ float g_Wi[L_ * D_ * D_];     // rna(W_in  * nw)
__device__ float g_Wo[L_ * D_ * D_];     // rna(W_out)
__device__ float g_Ws[L_ * D_ * D_];     // rna(W_skip * nw)
__device__ float g_W0r[D_ * KIN_];       // rna(W0)

// ---------------- PTX helpers ----------------
__device__ __forceinline__ uint32_t smem_u32(const void* p) {
    uint32_t a;
    asm("{ .reg .u64 t; cvta.to.shared.u64 t, %1; cvt.u32.u64 %0, t; }" : "=r"(a) : "l"(p));
    return a;
}
__device__ __forceinline__ uint32_t f2tf32(float x) {
    uint32_t r; asm("cvt.rna.tf32.f32 %0, %1;" : "=r"(r) : "f"(x)); return r;
}
__device__ __forceinline__ float rna(float x) { return __uint_as_float(f2tf32(x)); }

__device__ __forceinline__ void mma_tf32(float* c, const uint32_t* a, const uint32_t* b) {
    asm volatile(
        "mma.sync.aligned.m16n8k8.row.col.f32.tf32.tf32.f32 "
        "{%0,%1,%2,%3}, {%4,%5,%6,%7}, {%8,%9}, {%0,%1,%2,%3};"
        : "+f"(c[0]), "+f"(c[1]), "+f"(c[2]), "+f"(c[3])
        : "r"(a[0]), "r"(a[1]), "r"(a[2]), "r"(a[3]), "r"(b[0]), "r"(b[1]));
}
__device__ __forceinline__ void ldsm4(uint32_t* r, uint32_t addr) {
    asm volatile("ldmatrix.sync.aligned.m8n8.x4.shared.b16 {%0,%1,%2,%3}, [%4];"
                 : "=r"(r[0]), "=r"(r[1]), "=r"(r[2]), "=r"(r[3]) : "r"(addr));
}
__device__ __forceinline__ void cp16(uint32_t s, const float* g) {
    asm volatile("{ .reg .u64 gp; cvta.to.global.u64 gp, %1;\n\t"
                 "cp.async.cg.shared.global [%0], [gp], 16; }"
                 :: "r"(s), "l"(g) : "memory");
}
__device__ __forceinline__ void cp_commit() { asm volatile("cp.async.commit_group;" ::: "memory"); }
__device__ __forceinline__ void cp_wait0()  { asm volatile("cp.async.wait_group 0;" ::: "memory"); }
__device__ __forceinline__ void cp_wait1()  { asm volatile("cp.async.wait_group 1;" ::: "memory"); }
#define BARP(id) asm volatile("bar.sync %0, 64;" :: "r"(id) : "memory")

__device__ __forceinline__ float part_scale(const float* pin, int m) {
    float s = pin[m] + pin[M_BIG + m] + pin[2 * M_BIG + m] + pin[3 * M_BIG + m];
    return rsqrtf(s * (1.0f / 256.0f) + EPS_);
}

#define ACHUNK 4608              // 32*144

// pair-shared A staging: 32 rows x 32 k; each warp of the pair stages 16 rows
__device__ __forceinline__ void stage_pair(uint32_t dst, const float* Agrp, int k0, int nh) {
    int lane = threadIdx.x & 31;
    int row  = nh * 16 + (lane >> 1);
    int part = lane & 1;
    const float* p = Agrp + (size_t)row * 256 + k0 + part * 16;
    uint32_t d = dst + row * 144 + part * 64;
    cp16(d,      p);
    cp16(d + 16, p + 4);
    cp16(d + 32, p + 8);
    cp16(d + 48, p + 12);
}

// =========== GEMM1 + fused scan: 512 thr, 8 pair-groups, BN=64, 3 A bufs ===========
// smem: W 64x1040B = 66560 | 8 groups x 13824 (3 A bufs / epilogue Us+sc)
#define G1_WB    66560
#define G1_REG   13824
#define SM1_TOT  (G1_WB + 8 * G1_REG)      // 177152
__global__ __launch_bounds__(512, 1)
void k_gemm_scan(const float* __restrict__ P, const float* __restrict__ Wi,
                 const float* __restrict__ bi, const float* __restrict__ ld_,
                 const float* __restrict__ partIn, float* __restrict__ states)
{
    extern __shared__ float smf[];
    uint32_t sm32 = smem_u32(smf);
    const int tid = threadIdx.x, lane = tid & 31, w = tid >> 5;
    const int grp = w >> 1, nh = w & 1, bid = grp + 1;
    const int lr = lane & 7, lb8 = (lane >> 3) & 1, lb16 = (lane >> 4) & 1;
    const int gid = lane >> 2, tig = lane & 3;
    const int qb = blockIdx.y * 64;

    // persistent W quarter (64 n-rows x 256 k): 512 thr x 8 cp16
    {
        int r = tid >> 3, seg = tid & 7;
        const float* s = Wi + (size_t)(qb + r) * 256 + seg * 32;
        uint32_t d = sm32 + r * 1040 + seg * 128;
#pragma unroll
        for (int j = 0; j < 8; j++) cp16(d + j * 16, s + j * 4);
    }
    cp_commit(); cp_wait0();
    __syncthreads();

    const uint32_t AB = sm32 + G1_WB + grp * G1_REG;
    float* ABf = smf + (G1_WB / 4) + grp * (G1_REG / 4);

    for (int tile = blockIdx.x; tile < M_BIG / 256; tile += gridDim.x) {
        const int m0g = tile * 256 + grp * 32;
        const float* Am = P + (size_t)m0g * 256;

        stage_pair(AB,          Am, 0,  nh); cp_commit();
        stage_pair(AB + ACHUNK, Am, 32, nh); cp_commit();

        float acc[2][4][4];
#pragma unroll
        for (int mt = 0; mt < 2; mt++)
#pragma unroll
            for (int j = 0; j < 4; j++)
#pragma unroll
                for (int q = 0; q < 4; q++) acc[mt][j][q] = 0.f;

#pragma unroll 1
        for (int c = 0; c < 8; c++) {
            cp_wait1();            // chunk c staged (my half)
            BARP(bid);             // partner's half staged; partner past iter c-1
            // stage c+2 into buf (c+2)%3 == (c-1)%3 — last read iter c-1, safe
            if (c + 2 < 8) stage_pair(AB + ((c + 2) % 3) * ACHUNK, Am, (c + 2) * 32, nh);
            cp_commit();
            const uint32_t A0 = AB + (c % 3) * ACHUNK;
#pragma unroll
            for (int ks = 0; ks < 4; ks++) {
                uint32_t a[2][4];
                ldsm4(a[0], A0 + (lr + lb8 * 8) * 144 + lb16 * 16 + ks * 32);
                ldsm4(a[1], A0 + (16 + lr + lb8 * 8) * 144 + lb16 * 16 + ks * 32);
#pragma unroll
                for (int ng = 0; ng < 2; ng++) {
                    uint32_t bf[4];
                    ldsm4(bf, sm32 + (nh * 32 + ng * 16 + lr + lb16 * 8) * 1040
                              + lb8 * 16 + (c * 32 + ks * 8) * 4);
                    mma_tf32(acc[0][ng * 2],     a[0], &bf[0]);
                    mma_tf32(acc[0][ng * 2 + 1], a[0], &bf[2]);
                    mma_tf32(acc[1][ng * 2],     a[1], &bf[0]);
                    mma_tf32(acc[1][ng * 2 + 1], a[1], &bf[2]);
                }
            }
        }
        BARP(bid);   // pair done reading A bufs before Us overwrites region

        // epilogue: Us[32][64] per group; sc[32] after it
        float* Us = ABf;
        float* sc = ABf + 2048;
#pragma unroll
        for (int mt = 0; mt < 2; mt++) {
            int r = mt * 16 + gid;
#pragma unroll
            for (int j = 0; j < 4; j++) {
                int col = nh * 32 + j * 8 + tig * 2;
                Us[r * 64 + col]           = acc[mt][j][0];
                Us[r * 64 + col + 1]       = acc[mt][j][1];
                Us[(r + 8) * 64 + col]     = acc[mt][j][2];
                Us[(r + 8) * 64 + col + 1] = acc[mt][j][3];
            }
        }
        if (nh == 0) sc[lane] = part_scale(partIn, m0g + lane);
        BARP(bid);
        // scan along t: 2 batches x 64 cols = 128 chains / 64 lanes
#pragma unroll
        for (int q = 0; q < 2; q++) {
            int task = nh * 32 + lane + 64 * q;
            int bb = task >> 6, cc = task & 63;
            float dec = 1.0f / (1.0f + expf(-ld_[qb + cc]));
            float bias = bi[qb + cc];
            float st = 0.f;
#pragma unroll
            for (int tt = 0; tt < 16; tt++) {
                int row = bb * 16 + tt;
                float u = Us[row * 64 + cc] * sc[row] + bias;
                st = dec * st + u;
                Us[row * 64 + cc] = st;
            }
        }
        BARP(bid);
#pragma unroll
        for (int i = 0; i < 8; i++) {
            int f = nh * 32 + lane + 64 * i;
            int row = f >> 4, c4 = (f & 15) * 4;
            float4 v = *(float4*)&Us[row * 64 + c4];
            *(float4*)&states[(size_t)(m0g + row) * 256 + qb + c4] = v;
        }
        BARP(bid);
    }
}

// =========== GEMM2: 512 thr, 8 pair-groups, BN=64, K=512 ([Ws;Wo]), 2 A bufs ===========
// smem: W 64x2064B = 132096 | 8 groups x 9216
#define G2_WB    132096
#define G2_REG   9216
#define SM2_TOT  (G2_WB + 8 * G2_REG)      // 205824
__global__ __launch_bounds__(512, 1)
void k_gemm2(const float* __restrict__ P, const float* __restrict__ Wsp,
             const float* __restrict__ states, const float* __restrict__ Wo,
             const float* __restrict__ partIn,
             const float* __restrict__ bo, const float* __restrict__ bsk,
             float* __restrict__ Q, float* __restrict__ partOut)
{
    extern __shared__ float smf[];
    uint32_t sm32 = smem_u32(smf);
    const int tid = threadIdx.x, lane = tid & 31, w = tid >> 5;
    const int grp = w >> 1, nh = w & 1, bid = grp + 1;
    const int lr = lane & 7, lb8 = (lane >> 3) & 1, lb16 = (lane >> 4) & 1;
    const int gid = lane >> 2, tig = lane & 3;
    const int qb = blockIdx.y * 64;

    // persistent [Ws | Wo] quarter (64 n-rows x 512 k): 512 thr x 16 cp16
    {
        int r = tid >> 3, seg = tid & 7;
        int col64 = seg * 64;
        const float* s = (col64 < 256) ? (Wsp + (size_t)(qb + r) * 256 + col64)
                                       : (Wo  + (size_t)(qb + r) * 256 + col64 - 256);
        uint32_t d = sm32 + r * 2064 + col64 * 4;
#pragma unroll
        for (int j = 0; j < 16; j++) cp16(d + j * 16, s + j * 4);
    }
    cp_commit(); cp_wait0();
    __syncthreads();

    const uint32_t AB = sm32 + G2_WB + grp * G2_REG;
    float* ABf = smf + (G2_WB / 4) + grp * (G2_REG / 4);

    for (int tile = blockIdx.x; tile < M_BIG / 256; tile += gridDim.x) {
        const int m0g = tile * 256 + grp * 32;
        const float* Pm = P + (size_t)m0g * 256;
        const float* Sm = states + (size_t)m0g * 256;

        stage_pair(AB,          Pm, 0,  nh); cp_commit();
        stage_pair(AB + ACHUNK, Pm, 32, nh); cp_commit();

        float acc[2][4][4];
#pragma unroll
        for (int mt = 0; mt < 2; mt++)
#pragma unroll
            for (int j = 0; j < 4; j++)
#pragma unroll
                for (int q = 0; q < 4; q++) acc[mt][j][q] = 0.f;

#pragma unroll 1
        for (int c = 0; c < 16; c++) {
            cp_wait1();            // chunk c staged (my half)
            BARP(bid);             // both halves staged
            if (c == 8) {
                // finished x@Ws' half: apply rmsnorm row scales to acc
#pragma unroll
                for (int mt = 0; mt < 2; mt++) {
                    float s0 = part_scale(partIn, m0g + mt * 16 + gid);
                    float s1 = part_scale(partIn, m0g + mt * 16 + gid + 8);
#pragma unroll
                    for (int j = 0; j < 4; j++) {
                        acc[mt][j][0] *= s0; acc[mt][j][1] *= s0;
                        acc[mt][j][2] *= s1; acc[mt][j][3] *= s1;
                    }
                }
            }
            const uint32_t A0 = AB + (c & 1) * ACHUNK;
#pragma unroll
            for (int ks = 0; ks < 4; ks++) {
                uint32_t a[2][4];
                ldsm4(a[0], A0 + (lr + lb8 * 8) * 144 + lb16 * 16 + ks * 32);
                ldsm4(a[1], A0 + (16 + lr + lb8 * 8) * 144 + lb16 * 16 + ks * 32);
#pragma unroll
                for (int ng = 0; ng < 2; ng++) {
                    uint32_t bf[4];
                    ldsm4(bf, sm32 + (nh * 32 + ng * 16 + lr + lb16 * 8) * 2064
                              + lb8 * 16 + (c * 32 + ks * 8) * 4);
                    mma_tf32(acc[0][ng * 2],     a[0], &bf[0]);
                    mma_tf32(acc[0][ng * 2 + 1], a[0], &bf[2]);
                    mma_tf32(acc[1][ng * 2],     a[1], &bf[0]);
                    mma_tf32(acc[1][ng * 2 + 1], a[1], &bf[2]);
                }
            }
            BARP(bid);             // pair done reading buf c&1
            if (c + 2 < 16) {
                int cn = c + 2;
                stage_pair(AB + (c & 1) * ACHUNK, cn < 8 ? Pm : Sm, (cn & 7) * 32, nh);
            }
            cp_commit();
        }

        // epilogue: Us[32][64] per group (bufs free: trailing BARP of last iter)
        float* Us = ABf;
#pragma unroll
        for (int mt = 0; mt < 2; mt++) {
            int r = mt * 16 + gid;
#pragma unroll
            for (int j = 0; j < 4; j++) {
                int col = nh * 32 + j * 8 + tig * 2;
                float bb0 = bo[qb + col]     + bsk[qb + col];
                float bb1 = bo[qb + col + 1] + bsk[qb + col + 1];
                Us[r * 64 + col]           = acc[mt][j][0] + bb0;
                Us[r * 64 + col + 1]       = acc[mt][j][1] + bb1;
                Us[(r + 8) * 64 + col]     = acc[mt][j][2] + bb0;
                Us[(r + 8) * 64 + col + 1] = acc[mt][j][3] + bb1;
            }
        }
        BARP(bid);
        // residual + store + per-row partial sumsq over the group's n64
#pragma unroll
        for (int i = 0; i < 8; i++) {
            int f = nh * 32 + lane + 64 * i;
            int row = f >> 4, c4 = (f & 15) * 4;
            float4 v = *(float4*)&Us[row * 64 + c4];
            float4 p = *(const float4*)&Pm[(size_t)row * 256 + qb + c4];
            v.x += p.x; v.y += p.y; v.z += p.z; v.w += p.w;
            *(float4*)&Q[(size_t)(m0g + row) * 256 + qb + c4] = v;
            float s = v.x * v.x + v.y * v.y + v.z * v.z + v.w * v.w;
            s += __shfl_xor_sync(0xffffffffu, s, 1);
            s += __shfl_xor_sync(0xffffffffu, s, 2);
            s += __shfl_xor_sync(0xffffffffu, s, 4);
            s += __shfl_xor_sync(0xffffffffu, s, 8);
            if ((lane & 15) == 0)
                partOut[(size_t)blockIdx.y * M_BIG + m0g + row] = s;
        }
        BARP(bid);
    }
}

// =========== prologue / small kernels ===========
__global__ void prep_weights(const float* __restrict__ Wi, const float* __restrict__ Wo,
                             const float* __restrict__ Wsk, const float* __restrict__ nw,
                             const float* __restrict__ W0)
{
    int i = blockIdx.x * blockDim.x + threadIdx.x;
    if (i < L_ * D_ * D_) {
        int l = i >> 16, k = i & 255;
        float w = nw[l * D_ + k];
        g_Wi[i] = rna(Wi[i] * w);
        g_Ws[i] = rna(Wsk[i] * w);
        g_Wo[i] = rna(Wo[i]);
    }
    if (i < D_ * KIN_) g_W0r[i] = rna(W0[i]);
}

__global__ void shift_scale_kernel(const float* __restrict__ deter,
                                   float* __restrict__ tok, float* __restrict__ part0)
{
    int gw = (blockIdx.x * blockDim.x + threadIdx.x) >> 5;
    if (gw >= B_ * 15) return;
    int lane = threadIdx.x & 31;
    int b = gw / 15, t = gw - b * 15;
    const float4* src = (const float4*)(deter + (size_t)b * 4096 + (t + 1) * 256) + lane;
    float4* dst = (float4*)(tok + (size_t)b * 4096 + t * 256) + lane;
    float4 v0 = src[0], v1 = src[32];
    dst[0] = v0; dst[32] = v1;
    float s = v0.x*v0.x + v0.y*v0.y + v0.z*v0.z + v0.w*v0.w
            + v1.x*v1.x + v1.y*v1.y + v1.z*v1.z + v1.w*v1.w;
#pragma unroll
    for (int o = 16; o > 0; o >>= 1) s += __shfl_xor_sync(0xffffffffu, s, o);
    if (lane == 0) {
        int mm = b * 16 + t;
        part0[mm] = s;
        part0[M_BIG + mm] = 0.f;
        part0[2 * M_BIG + mm] = 0.f;
        part0[3 * M_BIG + mm] = 0.f;
    }
}

__global__ void concat_kernel(const float* __restrict__ stoch,
                              const float* __restrict__ action,
                              float* __restrict__ cat)
{
    int idx = blockIdx.x * blockDim.x + threadIdx.x;
    if (idx >= B_ * KIN_) return;
    int b = idx / KIN_;
    int k = idx - b * KIN_;
    float v;
    if (k < 1024) v = stoch[(size_t)b * 1024 + k];
    else {
        float a = action[(size_t)b * 32 + (k - 1024)];
        v = a / fmaxf(fabsf(a), 1.0f);
    }
    cat[idx] = v;
}

__global__ void apply_norm_kernel(const float* __restrict__ in, const float* __restrict__ w,
                                  float* __restrict__ out)
{
    int gw = (blockIdx.x * blockDim.x + threadIdx.x) >> 5;
    int lane = threadIdx.x & 31;
    const float* rp = in + (size_t)gw * 256 + lane * 8;
    float v[8];
    *(float4*)&v[0] = *(const float4*)rp;
    *(float4*)&v[4] = *(const float4*)(rp + 4);
    float s = 0.f;
#pragma unroll
    for (int j = 0; j < 8; j++) s += v[j] * v[j];
#pragma unroll
    for (int o = 16; o > 0; o >>= 1) s += __shfl_xor_sync(0xffffffffu, s, o);
    float sc = rsqrtf(s * (1.0f / 256.0f) + EPS_);
    float wl[8];
    *(float4*)&wl[0] = *(const float4*)(w + lane * 8);
    *(float4*)&wl[4] = *(const float4*)(w + lane * 8 + 4);
    float o8[8];
#pragma unroll
    for (int j = 0; j < 8; j++) o8[j] = v[j] * sc * wl[j];
    float* op = out + (size_t)gw * 256 + lane * 8;
    *(float4*)op = *(float4*)&o8[0];
    *(float4*)(op + 4) = *(float4*)&o8[4];
}

// =========== input proj: BM=32, 128 CTAs ===========
#define SMP_A0   0
#define SMP_A1   4608
#define SMP_B0   9216
#define SMP_B1   46080
#define SMP_TOT  82944

__device__ __forceinline__ void stage_chunk_p(uint32_t sm32, int buf,
                                              const float* A, const float* W, int k0)
{
    const int tid = threadIdx.x;
    {
        int row = tid >> 3, kc = (tid & 7) * 4;
        const float* p = A + (size_t)row * KIN_ + k0 + kc;
        uint32_t d = sm32 + (buf ? SMP_A1 : SMP_A0) + row * 144 + kc * 4;
        cp16(d, p);
    }
    {
        const float* p = W + (size_t)tid * KIN_ + k0;
        uint32_t d = sm32 + (buf ? SMP_B1 : SMP_B0) + tid * 144;
#pragma unroll
        for (int j = 0; j < 8; j++) cp16(d + j * 16, p + j * 4);
    }
}

__global__ __launch_bounds__(256, 2)
void k_proj(const float* __restrict__ cat, const float* __restrict__ b0,
            const float* __restrict__ g0, float* __restrict__ tokA,
            float* __restrict__ part0)
{
    extern __shared__ float smf[];
    uint32_t sm32 = smem_u32(smf);
    const int tid = threadIdx.x, wid = tid >> 5, lane = tid & 31;
    const int wm = wid & 1, wn = wid >> 1;
    const int gid = lane >> 2, tig = lane & 3;
    const int lr = lane & 7, lb8 = (lane >> 3) & 1, lb16 = (lane >> 4) & 1;
    const int m0 = blockIdx.x * 32;
    const float* A = cat + (size_t)m0 * KIN_;

    const uint32_t aoff = (uint32_t)(wm * 16 + lr + lb8 * 8) * 144 + lb16 * 16;
    const uint32_t boff = (uint32_t)(wn * 64 + lr + lb16 * 8) * 144 + lb8 * 16;

    float acc[8][4];
#pragma unroll
    for (int j = 0; j < 8; j++)
#pragma unroll
        for (int q = 0; q < 4; q++) acc[j][q] = 0.f;

    stage_chunk_p(sm32, 0, A, g_W0r, 0);
    cp_commit();
#pragma unroll 1
    for (int i = 0; i < 33; i++) {
        const int b = i & 1;
        if (i + 1 < 33) {
            stage_chunk_p(sm32, (i + 1) & 1, A, g_W0r, (i + 1) * 32);
            cp_commit();
            cp_wait1();
        } else cp_wait0();
        __syncthreads();
        const uint32_t sA = sm32 + (b ? SMP_A1 : SMP_A0);
        const uint32_t sB = sm32 + (b ? SMP_B1 : SMP_B0);
#pragma unroll
        for (int ks = 0; ks < 4; ks++) {
            uint32_t a0[4], bf[4][4];
            ldsm4(a0, sA + aoff + ks * 32);
#pragma unroll
            for (int pr = 0; pr < 4; pr++)
                ldsm4(bf[pr], sB + boff + pr * 2304 + ks * 32);
#pragma unroll
            for (int pr = 0; pr < 4; pr++) {
                mma_tf32(acc[2*pr],   a0, &bf[pr][0]);
                mma_tf32(acc[2*pr+1], a0, &bf[pr][2]);
            }
        }
        __syncthreads();
    }

    float* Us = smf;   // [32][260]
#pragma unroll
    for (int j = 0; j < 8; j++) {
        int r = wm * 16 + gid;
        int col = wn * 64 + j * 8 + tig * 2;
        Us[r * 260 + col]           = acc[j][0];
        Us[r * 260 + col + 1]       = acc[j][1];
        Us[(r + 8) * 260 + col]     = acc[j][2];
        Us[(r + 8) * 260 + col + 1] = acc[j][3];
    }
    __syncthreads();
#pragma unroll
    for (int k = 0; k < 4; k++) {
        int row = k * 8 + wid;
        int m = m0 + row;
        float v[8]; float sum = 0.f;
#pragma unroll
        for (int j = 0; j < 8; j++) {
            int c = lane + 32 * j;
            v[j] = Us[row * 260 + c] + b0[c];
            sum += v[j] * v[j];
        }
#pragma unroll
        for (int o = 16; o > 0; o >>= 1) sum += __shfl_xor_sync(0xffffffffu, sum, o);
        float sc = rsqrtf(sum * (1.0f / 256.0f) + EPS_);
        float s2 = 0.f;
#pragma unroll
        for (int j = 0; j < 8; j++) {
            int c = lane + 32 * j;
            float y = v[j] * sc * g0[c];
            y = y / (1.0f + expf(-y));
            s2 += y * y;
            tokA[(size_t)m * 4096 + 3840 + c] = y;
        }
#pragma unroll
        for (int o = 16; o > 0; o >>= 1) s2 += __shfl_xor_sync(0xffffffffu, s2, o);
        if (lane == 0) {
            int mm = m * 16 + 15;
            part0[mm] = s2;
            part0[M_BIG + mm] = 0.f;
            part0[2 * M_BIG + mm] = 0.f;
            part0[3 * M_BIG + mm] = 0.f;
        }
    }
}

// ---------------- launch ----------------
extern "C" void kernel_launch(void* const* d_in, const int* in_sizes, int n_in,
                              void* d_out, int out_size)
{
    const float* stoch      = (const float*)d_in[0];
    const float* deter      = (const float*)d_in[1];
    const float* action     = (const float*)d_in[2];
    const float* W0         = (const float*)d_in[3];
    const float* b0         = (const float*)d_in[4];
    const float* g0         = (const float*)d_in[5];
    const float* norm_w     = (const float*)d_in[6];
    const float* W_in       = (const float*)d_in[7];
    const float* b_in       = (const float*)d_in[8];
    const float* W_out      = (const float*)d_in[9];
    const float* b_out      = (const float*)d_in[10];
    const float* W_skip     = (const float*)d_in[11];
    const float* b_skip     = (const float*)d_in[12];
    const float* log_decay  = (const float*)d_in[13];
    const float* out_norm_w = (const float*)d_in[14];
    float* out = (float*)d_out;

    float *tokA, *tokB, *states, *cat, *part, *Wi_s, *Wo_s, *Ws_s;
    cudaGetSymbolAddress((void**)&tokA,   g_tokA);
    cudaGetSymbolAddress((void**)&tokB,   g_tokB);
    cudaGetSymbolAddress((void**)&states, g_states);
    cudaGetSymbolAddress((void**)&cat,    g_cat);
    cudaGetSymbolAddress((void**)&part,   g_part);
    cudaGetSymbolAddress((void**)&Wi_s,   g_Wi);
    cudaGetSymbolAddress((void**)&Wo_s,   g_Wo);
    cudaGetSymbolAddress((void**)&Ws_s,   g_Ws);

    cudaFuncSetAttribute(k_proj,      cudaFuncAttributeMaxDynamicSharedMemorySize, SMP_TOT);
    cudaFuncSetAttribute(k_gemm_scan, cudaFuncAttributeMaxDynamicSharedMemorySize, SM1_TOT);
    cudaFuncSetAttribute(k_gemm2,     cudaFuncAttributeMaxDynamicSharedMemorySize, SM2_TOT);

    prep_weights<<<(D_ * KIN_ + 255) / 256 + 1, 256>>>(W_in, W_out, W_skip, norm_w, W0);
    shift_scale_kernel<<<B_ * 15 / 8, 256>>>(deter, tokA, part);
    concat_kernel<<<(B_ * KIN_ + 255) / 256, 256>>>(stoch, action, cat);
    k_proj<<<B_ / 32, 256, SMP_TOT>>>(cat, b0, g0, tokA, part);

    float* Pb = tokA;
    float* Qb = tokB;
    for (int l = 0; l < L_; l++) {
        const float* Wi  = Wi_s + (size_t)l * D_ * D_;
        const float* Wo  = Wo_s + (size_t)l * D_ * D_;
        const float* Ws  = Ws_s + (size_t)l * D_ * D_;
        const float* bi  = b_in      + (size_t)l * D_;
        const float* bo  = b_out     + (size_t)l * D_;
        const float* bsk = b_skip    + (size_t)l * D_;
        const float* ld  = log_decay + (size_t)l * D_;
        float* partIn  = part + (size_t)(l & 1) * 4 * M_BIG;
        float* partOut = part + (size_t)((l + 1) & 1) * 4 * M_BIG;

        k_gemm_scan<<<dim3(37, 4), 512, SM1_TOT>>>(Pb, Wi, bi, ld, partIn, states);
        k_gemm2<<<dim3(37, 4), 512, SM2_TOT>>>(Pb, Ws, states, Wo, partIn,
                                               bo, bsk, Qb, partOut);
        float* tmp = Pb; Pb = Qb; Qb = tmp;
    }

    apply_norm_kernel<<<M_BIG / 8, 256>>>(Pb, out_norm_w, out);
}

// round 11
// speedup vs baseline: 1.4728x; 1.0253x over previous
#include <cuda_runtime.h>
#include <math.h>
#include <stdint.h>

#define B_    4096
#define T_    16
#define D_    256
#define L_    4
#define KIN_  1056
#define EPS_  1e-4f
#define M_BIG (B_ * T_)          // 65536

// ---------------- scratch ----------------
__device__ float g_tokA[M_BIG * D_];
__device__ float g_tokB[M_BIG * D_];
__device__ float g_states[M_BIG * D_];
__device__ float g_cat[B_ * KIN_];
__device__ float g_part[2][4 * M_BIG];   // per-quarter partial sum-of-squares
__device__ float g_Wi[L_ * D_ * D_];     // rna(W_in  * nw)
__device__ float g_Wo[L_ * D_ * D_];     // rna(W_out)
__device__ float g_Ws[L_ * D_ * D_];     // rna(W_skip * nw)
__device__ float g_W0r[D_ * KIN_];       // rna(W0)

// ---------------- PTX helpers ----------------
__device__ __forceinline__ uint32_t smem_u32(const void* p) {
    uint32_t a;
    asm("{ .reg .u64 t; cvta.to.shared.u64 t, %1; cvt.u32.u64 %0, t; }" : "=r"(a) : "l"(p));
    return a;
}
__device__ __forceinline__ uint32_t f2tf32(float x) {
    uint32_t r; asm("cvt.rna.tf32.f32 %0, %1;" : "=r"(r) : "f"(x)); return r;
}
__device__ __forceinline__ float rna(float x) { return __uint_as_float(f2tf32(x)); }

__device__ __forceinline__ void mma_tf32(float* c, const uint32_t* a, const uint32_t* b) {
    asm volatile(
        "mma.sync.aligned.m16n8k8.row.col.f32.tf32.tf32.f32 "
        "{%0,%1,%2,%3}, {%4,%5,%6,%7}, {%8,%9}, {%0,%1,%2,%3};"
        : "+f"(c[0]), "+f"(c[1]), "+f"(c[2]), "+f"(c[3])
        : "r"(a[0]), "r"(a[1]), "r"(a[2]), "r"(a[3]), "r"(b[0]), "r"(b[1]));
}
__device__ __forceinline__ void ldsm4(uint32_t* r, uint32_t addr) {
    asm volatile("ldmatrix.sync.aligned.m8n8.x4.shared.b16 {%0,%1,%2,%3}, [%4];"
                 : "=r"(r[0]), "=r"(r[1]), "=r"(r[2]), "=r"(r[3]) : "r"(addr));
}
__device__ __forceinline__ void cp16(uint32_t s, const float* g) {
    asm volatile("{ .reg .u64 gp; cvta.to.global.u64 gp, %1;\n\t"
                 "cp.async.cg.shared.global [%0], [gp], 16; }"
                 :: "r"(s), "l"(g) : "memory");
}
__device__ __forceinline__ void cp_commit() { asm volatile("cp.async.commit_group;" ::: "memory"); }
__device__ __forceinline__ void cp_wait0()  { asm volatile("cp.async.wait_group 0;" ::: "memory"); }
__device__ __forceinline__ void cp_wait1()  { asm volatile("cp.async.wait_group 1;" ::: "memory"); }
#define BARP(id) asm volatile("bar.sync %0, 64;" :: "r"(id) : "memory")

__device__ __forceinline__ float part_scale(const float* pin, int m) {
    float s = pin[m] + pin[M_BIG + m] + pin[2 * M_BIG + m] + pin[3 * M_BIG + m];
    return rsqrtf(s * (1.0f / 256.0f) + EPS_);
}

#define ACHUNK 4608              // 32*144

// pair-shared A staging: 32 rows x 32 k; each warp of the pair stages 16 rows
__device__ __forceinline__ void stage_pair(uint32_t dst, const float* Agrp, int k0, int nh) {
    int lane = threadIdx.x & 31;
    int row  = nh * 16 + (lane >> 1);
    int part = lane & 1;
    const float* p = Agrp + (size_t)row * 256 + k0 + part * 16;
    uint32_t d = dst + row * 144 + part * 64;
    cp16(d,      p);
    cp16(d + 16, p + 4);
    cp16(d + 32, p + 8);
    cp16(d + 48, p + 12);
}

// =========== GEMM1 + fused scan: 512 thr, 8 groups, BN=128, grid.y=2, 2 A bufs ===========
// smem: W 128x1040B = 133120 | 8 groups x 9216 (2 A bufs, reused as warp epilogue)
#define G1_WB    133120
#define G1_REG   9216
#define SM1_TOT  (G1_WB + 8 * G1_REG)      // 206848
__global__ __launch_bounds__(512, 1)
void k_gemm_scan(const float* __restrict__ P, const float* __restrict__ Wi,
                 const float* __restrict__ bi, const float* __restrict__ ld_,
                 const float* __restrict__ partIn, float* __restrict__ states)
{
    extern __shared__ float smf[];
    uint32_t sm32 = smem_u32(smf);
    const int tid = threadIdx.x, lane = tid & 31, w = tid >> 5;
    const int grp = w >> 1, nh = w & 1, bid = grp + 1;
    const int lr = lane & 7, lb8 = (lane >> 3) & 1, lb16 = (lane >> 4) & 1;
    const int gid = lane >> 2, tig = lane & 3;
    const int qb = blockIdx.y * 128;

    // persistent W half (128 n-rows x 256 k): 512 thr x 16 cp16
    {
        int r = tid >> 2, seg = tid & 3;
        const float* s = Wi + (size_t)(qb + r) * 256 + seg * 64;
        uint32_t d = sm32 + r * 1040 + seg * 256;
#pragma unroll
        for (int j = 0; j < 16; j++) cp16(d + j * 16, s + j * 4);
    }
    cp_commit(); cp_wait0();
    __syncthreads();

    const uint32_t AB = sm32 + G1_WB + grp * G1_REG;
    float* ABf = smf + (G1_WB / 4) + grp * (G1_REG / 4);

    for (int tile = blockIdx.x; tile < M_BIG / 256; tile += gridDim.x) {
        const int m0g = tile * 256 + grp * 32;
        const float* Am = P + (size_t)m0g * 256;

        stage_pair(AB,          Am, 0,  nh); cp_commit();
        stage_pair(AB + ACHUNK, Am, 32, nh); cp_commit();

        float acc[2][8][4];
#pragma unroll
        for (int mt = 0; mt < 2; mt++)
#pragma unroll
            for (int j = 0; j < 8; j++)
#pragma unroll
                for (int q = 0; q < 4; q++) acc[mt][j][q] = 0.f;

#pragma unroll 1
        for (int c = 0; c < 8; c++) {
            cp_wait1();            // chunk c staged (my half)
            BARP(bid);             // partner's half staged
            const uint32_t A0 = AB + (c & 1) * ACHUNK;
#pragma unroll
            for (int ks = 0; ks < 4; ks++) {
                uint32_t a[2][4];
                ldsm4(a[0], A0 + (lr + lb8 * 8) * 144 + lb16 * 16 + ks * 32);
                ldsm4(a[1], A0 + (16 + lr + lb8 * 8) * 144 + lb16 * 16 + ks * 32);
#pragma unroll
                for (int ng = 0; ng < 4; ng++) {
                    uint32_t bf[4];
                    ldsm4(bf, sm32 + (nh * 64 + ng * 16 + lr + lb16 * 8) * 1040
                              + lb8 * 16 + (c * 32 + ks * 8) * 4);
                    mma_tf32(acc[0][ng * 2],     a[0], &bf[0]);
                    mma_tf32(acc[0][ng * 2 + 1], a[0], &bf[2]);
                    mma_tf32(acc[1][ng * 2],     a[1], &bf[0]);
                    mma_tf32(acc[1][ng * 2 + 1], a[1], &bf[2]);
                }
            }
            BARP(bid);             // pair done reading buf c&1
            if (c + 2 < 8) stage_pair(AB + (c & 1) * ACHUNK, Am, (c + 2) * 32, nh);
            cp_commit();
        }
        // after final second BARP: partner finished all compute; epilogue is warp-local.
        // warp nh's slice: ABf + nh*1152 floats (4608 B): Us 16x64 (4096B) + sc 16 (64B)
        float* Uw = ABf + nh * 1152;
#pragma unroll
        for (int mt = 0; mt < 2; mt++) {
            // write acc m16-half (rows = gid, gid+8; batch m0g + mt*16 .. +15)
#pragma unroll
            for (int j = 0; j < 8; j++) {
                int col = j * 8 + tig * 2;
                Uw[gid * 64 + col]           = acc[mt][j][0];
                Uw[gid * 64 + col + 1]       = acc[mt][j][1];
                Uw[(gid + 8) * 64 + col]     = acc[mt][j][2];
                Uw[(gid + 8) * 64 + col + 1] = acc[mt][j][3];
            }
            if (lane < 16) Uw[1024 + lane] = part_scale(partIn, m0g + mt * 16 + lane);
            __syncwarp();
            // scan over t=16 rows; 2 cols per lane; global col = qb + nh*64 + cc
#pragma unroll
            for (int q = 0; q < 2; q++) {
                int cc = lane + 32 * q;
                int gc = qb + nh * 64 + cc;
                float dec = 1.0f / (1.0f + expf(-ld_[gc]));
                float bias = bi[gc];
                float st = 0.f;
#pragma unroll
                for (int tt = 0; tt < 16; tt++) {
                    float u = Uw[tt * 64 + cc] * Uw[1024 + tt] + bias;
                    st = dec * st + u;
                    Uw[tt * 64 + cc] = st;
                }
            }
            __syncwarp();
            // coalesced store: 16 rows x 16 float4 = 256 float4 / 32 lanes
#pragma unroll
            for (int i = 0; i < 8; i++) {
                int f = lane + 32 * i;
                int row = f >> 4, c4 = (f & 15) * 4;
                float4 v = *(float4*)&Uw[row * 64 + c4];
                *(float4*)&states[(size_t)(m0g + mt * 16 + row) * 256
                                  + qb + nh * 64 + c4] = v;
            }
            __syncwarp();
        }
        BARP(bid);   // partner epilogue done before next tile's staging overwrites
    }
}

// =========== GEMM2: 512 thr, 8 pair-groups, BN=64, K=512 ([Ws;Wo]), 2 A bufs ===========
// smem: W 64x2064B = 132096 | 8 groups x 9216
#define G2_WB    132096
#define G2_REG   9216
#define SM2_TOT  (G2_WB + 8 * G2_REG)      // 205824
__global__ __launch_bounds__(512, 1)
void k_gemm2(const float* __restrict__ P, const float* __restrict__ Wsp,
             const float* __restrict__ states, const float* __restrict__ Wo,
             const float* __restrict__ partIn,
             const float* __restrict__ bo, const float* __restrict__ bsk,
             float* __restrict__ Q, float* __restrict__ partOut)
{
    extern __shared__ float smf[];
    uint32_t sm32 = smem_u32(smf);
    const int tid = threadIdx.x, lane = tid & 31, w = tid >> 5;
    const int grp = w >> 1, nh = w & 1, bid = grp + 1;
    const int lr = lane & 7, lb8 = (lane >> 3) & 1, lb16 = (lane >> 4) & 1;
    const int gid = lane >> 2, tig = lane & 3;
    const int qb = blockIdx.y * 64;

    // persistent [Ws | Wo] quarter (64 n-rows x 512 k): 512 thr x 16 cp16
    {
        int r = tid >> 3, seg = tid & 7;
        int col64 = seg * 64;
        const float* s = (col64 < 256) ? (Wsp + (size_t)(qb + r) * 256 + col64)
                                       : (Wo  + (size_t)(qb + r) * 256 + col64 - 256);
        uint32_t d = sm32 + r * 2064 + col64 * 4;
#pragma unroll
        for (int j = 0; j < 16; j++) cp16(d + j * 16, s + j * 4);
    }
    cp_commit(); cp_wait0();
    __syncthreads();

    const uint32_t AB = sm32 + G2_WB + grp * G2_REG;
    float* ABf = smf + (G2_WB / 4) + grp * (G2_REG / 4);

    for (int tile = blockIdx.x; tile < M_BIG / 256; tile += gridDim.x) {
        const int m0g = tile * 256 + grp * 32;
        const float* Pm = P + (size_t)m0g * 256;
        const float* Sm = states + (size_t)m0g * 256;

        stage_pair(AB,          Pm, 0,  nh); cp_commit();
        stage_pair(AB + ACHUNK, Pm, 32, nh); cp_commit();

        float acc[2][4][4];
#pragma unroll
        for (int mt = 0; mt < 2; mt++)
#pragma unroll
            for (int j = 0; j < 4; j++)
#pragma unroll
                for (int q = 0; q < 4; q++) acc[mt][j][q] = 0.f;

#pragma unroll 1
        for (int c = 0; c < 16; c++) {
            cp_wait1();            // chunk c staged (my half)
            BARP(bid);             // both halves staged
            if (c == 8) {
                // finished x@Ws' half: apply rmsnorm row scales to acc
#pragma unroll
                for (int mt = 0; mt < 2; mt++) {
                    float s0 = part_scale(partIn, m0g + mt * 16 + gid);
                    float s1 = part_scale(partIn, m0g + mt * 16 + gid + 8);
#pragma unroll
                    for (int j = 0; j < 4; j++) {
                        acc[mt][j][0] *= s0; acc[mt][j][1] *= s0;
                        acc[mt][j][2] *= s1; acc[mt][j][3] *= s1;
                    }
                }
            }
            const uint32_t A0 = AB + (c & 1) * ACHUNK;
#pragma unroll
            for (int ks = 0; ks < 4; ks++) {
                uint32_t a[2][4];
                ldsm4(a[0], A0 + (lr + lb8 * 8) * 144 + lb16 * 16 + ks * 32);
                ldsm4(a[1], A0 + (16 + lr + lb8 * 8) * 144 + lb16 * 16 + ks * 32);
#pragma unroll
                for (int ng = 0; ng < 2; ng++) {
                    uint32_t bf[4];
                    ldsm4(bf, sm32 + (nh * 32 + ng * 16 + lr + lb16 * 8) * 2064
                              + lb8 * 16 + (c * 32 + ks * 8) * 4);
                    mma_tf32(acc[0][ng * 2],     a[0], &bf[0]);
                    mma_tf32(acc[0][ng * 2 + 1], a[0], &bf[2]);
                    mma_tf32(acc[1][ng * 2],     a[1], &bf[0]);
                    mma_tf32(acc[1][ng * 2 + 1], a[1], &bf[2]);
                }
            }
            BARP(bid);             // pair done reading buf c&1
            if (c + 2 < 16) {
                int cn = c + 2;
                stage_pair(AB + (c & 1) * ACHUNK, cn < 8 ? Pm : Sm, (cn & 7) * 32, nh);
            }
            cp_commit();
        }

        // epilogue: Us[32][64] per group (bufs free: trailing BARP of last iter)
        float* Us = ABf;
#pragma unroll
        for (int mt = 0; mt < 2; mt++) {
            int r = mt * 16 + gid;
#pragma unroll
            for (int j = 0; j < 4; j++) {
                int col = nh * 32 + j * 8 + tig * 2;
                float bb0 = bo[qb + col]     + bsk[qb + col];
                float bb1 = bo[qb + col + 1] + bsk[qb + col + 1];
                Us[r * 64 + col]           = acc[mt][j][0] + bb0;
                Us[r * 64 + col + 1]       = acc[mt][j][1] + bb1;
                Us[(r + 8) * 64 + col]     = acc[mt][j][2] + bb0;
                Us[(r + 8) * 64 + col + 1] = acc[mt][j][3] + bb1;
            }
        }
        BARP(bid);
        // residual + store + per-row partial sumsq over the group's n64
#pragma unroll
        for (int i = 0; i < 8; i++) {
            int f = nh * 32 + lane + 64 * i;
            int row = f >> 4, c4 = (f & 15) * 4;
            float4 v = *(float4*)&Us[row * 64 + c4];
            float4 p = *(const float4*)&Pm[(size_t)row * 256 + qb + c4];
            v.x += p.x; v.y += p.y; v.z += p.z; v.w += p.w;
            *(float4*)&Q[(size_t)(m0g + row) * 256 + qb + c4] = v;
            float s = v.x * v.x + v.y * v.y + v.z * v.z + v.w * v.w;
            s += __shfl_xor_sync(0xffffffffu, s, 1);
            s += __shfl_xor_sync(0xffffffffu, s, 2);
            s += __shfl_xor_sync(0xffffffffu, s, 4);
            s += __shfl_xor_sync(0xffffffffu, s, 8);
            if ((lane & 15) == 0)
                partOut[(size_t)blockIdx.y * M_BIG + m0g + row] = s;
        }
        BARP(bid);
    }
}

// =========== prologue / small kernels ===========
__global__ void prep_weights(const float* __restrict__ Wi, const float* __restrict__ Wo,
                             const float* __restrict__ Wsk, const float* __restrict__ nw,
                             const float* __restrict__ W0)
{
    int i = blockIdx.x * blockDim.x + threadIdx.x;
    if (i < L_ * D_ * D_) {
        int l = i >> 16, k = i & 255;
        float w = nw[l * D_ + k];
        g_Wi[i] = rna(Wi[i] * w);
        g_Ws[i] = rna(Wsk[i] * w);
        g_Wo[i] = rna(Wo[i]);
    }
    if (i < D_ * KIN_) g_W0r[i] = rna(W0[i]);
}

__global__ void shift_scale_kernel(const float* __restrict__ deter,
                                   float* __restrict__ tok, float* __restrict__ part0)
{
    int gw = (blockIdx.x * blockDim.x + threadIdx.x) >> 5;
    if (gw >= B_ * 15) return;
    int lane = threadIdx.x & 31;
    int b = gw / 15, t = gw - b * 15;
    const float4* src = (const float4*)(deter + (size_t)b * 4096 + (t + 1) * 256) + lane;
    float4* dst = (float4*)(tok + (size_t)b * 4096 + t * 256) + lane;
    float4 v0 = src[0], v1 = src[32];
    dst[0] = v0; dst[32] = v1;
    float s = v0.x*v0.x + v0.y*v0.y + v0.z*v0.z + v0.w*v0.w
            + v1.x*v1.x + v1.y*v1.y + v1.z*v1.z + v1.w*v1.w;
#pragma unroll
    for (int o = 16; o > 0; o >>= 1) s += __shfl_xor_sync(0xffffffffu, s, o);
    if (lane == 0) {
        int mm = b * 16 + t;
        part0[mm] = s;
        part0[M_BIG + mm] = 0.f;
        part0[2 * M_BIG + mm] = 0.f;
        part0[3 * M_BIG + mm] = 0.f;
    }
}

__global__ void concat_kernel(const float* __restrict__ stoch,
                              const float* __restrict__ action,
                              float* __restrict__ cat)
{
    int idx = blockIdx.x * blockDim.x + threadIdx.x;
    if (idx >= B_ * KIN_) return;
    int b = idx / KIN_;
    int k = idx - b * KIN_;
    float v;
    if (k < 1024) v = stoch[(size_t)b * 1024 + k];
    else {
        float a = action[(size_t)b * 32 + (k - 1024)];
        v = a / fmaxf(fabsf(a), 1.0f);
    }
    cat[idx] = v;
}

__global__ void apply_norm_kernel(const float* __restrict__ in, const float* __restrict__ w,
                                  float* __restrict__ out)
{
    int gw = (blockIdx.x * blockDim.x + threadIdx.x) >> 5;
    int lane = threadIdx.x & 31;
    const float* rp = in + (size_t)gw * 256 + lane * 8;
    float v[8];
    *(float4*)&v[0] = *(const float4*)rp;
    *(float4*)&v[4] = *(const float4*)(rp + 4);
    float s = 0.f;
#pragma unroll
    for (int j = 0; j < 8; j++) s += v[j] * v[j];
#pragma unroll
    for (int o = 16; o > 0; o >>= 1) s += __shfl_xor_sync(0xffffffffu, s, o);
    float sc = rsqrtf(s * (1.0f / 256.0f) + EPS_);
    float wl[8];
    *(float4*)&wl[0] = *(const float4*)(w + lane * 8);
    *(float4*)&wl[4] = *(const float4*)(w + lane * 8 + 4);
    float o8[8];
#pragma unroll
    for (int j = 0; j < 8; j++) o8[j] = v[j] * sc * wl[j];
    float* op = out + (size_t)gw * 256 + lane * 8;
    *(float4*)op = *(float4*)&o8[0];
    *(float4*)(op + 4) = *(float4*)&o8[4];
}

// =========== input proj: BM=32, 128 CTAs ===========
#define SMP_A0   0
#define SMP_A1   4608
#define SMP_B0   9216
#define SMP_B1   46080
#define SMP_TOT  82944

__device__ __forceinline__ void stage_chunk_p(uint32_t sm32, int buf,
                                              const float* A, const float* W, int k0)
{
    const int tid = threadIdx.x;
    {
        int row = tid >> 3, kc = (tid & 7) * 4;
        const float* p = A + (size_t)row * KIN_ + k0 + kc;
        uint32_t d = sm32 + (buf ? SMP_A1 : SMP_A0) + row * 144 + kc * 4;
        cp16(d, p);
    }
    {
        const float* p = W + (size_t)tid * KIN_ + k0;
        uint32_t d = sm32 + (buf ? SMP_B1 : SMP_B0) + tid * 144;
#pragma unroll
        for (int j = 0; j < 8; j++) cp16(d + j * 16, p + j * 4);
    }
}

__global__ __launch_bounds__(256, 2)
void k_proj(const float* __restrict__ cat, const float* __restrict__ b0,
            const float* __restrict__ g0, float* __restrict__ tokA,
            float* __restrict__ part0)
{
    extern __shared__ float smf[];
    uint32_t sm32 = smem_u32(smf);
    const int tid = threadIdx.x, wid = tid >> 5, lane = tid & 31;
    const int wm = wid & 1, wn = wid >> 1;
    const int gid = lane >> 2, tig = lane & 3;
    const int lr = lane & 7, lb8 = (lane >> 3) & 1, lb16 = (lane >> 4) & 1;
    const int m0 = blockIdx.x * 32;
    const float* A = cat + (size_t)m0 * KIN_;

    const uint32_t aoff = (uint32_t)(wm * 16 + lr + lb8 * 8) * 144 + lb16 * 16;
    const uint32_t boff = (uint32_t)(wn * 64 + lr + lb16 * 8) * 144 + lb8 * 16;

    float acc[8][4];
#pragma unroll
    for (int j = 0; j < 8; j++)
#pragma unroll
        for (int q = 0; q < 4; q++) acc[j][q] = 0.f;

    stage_chunk_p(sm32, 0, A, g_W0r, 0);
    cp_commit();
#pragma unroll 1
    for (int i = 0; i < 33; i++) {
        const int b = i & 1;
        if (i + 1 < 33) {
            stage_chunk_p(sm32, (i + 1) & 1, A, g_W0r, (i + 1) * 32);
            cp_commit();
            cp_wait1();
        } else cp_wait0();
        __syncthreads();
        const uint32_t sA = sm32 + (b ? SMP_A1 : SMP_A0);
        const uint32_t sB = sm32 + (b ? SMP_B1 : SMP_B0);
#pragma unroll
        for (int ks = 0; ks < 4; ks++) {
            uint32_t a0[4], bf[4][4];
            ldsm4(a0, sA + aoff + ks * 32);
#pragma unroll
            for (int pr = 0; pr < 4; pr++)
                ldsm4(bf[pr], sB + boff + pr * 2304 + ks * 32);
#pragma unroll
            for (int pr = 0; pr < 4; pr++) {
                mma_tf32(acc[2*pr],   a0, &bf[pr][0]);
                mma_tf32(acc[2*pr+1], a0, &bf[pr][2]);
            }
        }
        __syncthreads();
    }

    float* Us = smf;   // [32][260]
#pragma unroll
    for (int j = 0; j < 8; j++) {
        int r = wm * 16 + gid;
        int col = wn * 64 + j * 8 + tig * 2;
        Us[r * 260 + col]           = acc[j][0];
        Us[r * 260 + col + 1]       = acc[j][1];
        Us[(r + 8) * 260 + col]     = acc[j][2];
        Us[(r + 8) * 260 + col + 1] = acc[j][3];
    }
    __syncthreads();
#pragma unroll
    for (int k = 0; k < 4; k++) {
        int row = k * 8 + wid;
        int m = m0 + row;
        float v[8]; float sum = 0.f;
#pragma unroll
        for (int j = 0; j < 8; j++) {
            int c = lane + 32 * j;
            v[j] = Us[row * 260 + c] + b0[c];
            sum += v[j] * v[j];
        }
#pragma unroll
        for (int o = 16; o > 0; o >>= 1) sum += __shfl_xor_sync(0xffffffffu, sum, o);
        float sc = rsqrtf(sum * (1.0f / 256.0f) + EPS_);
        float s2 = 0.f;
#pragma unroll
        for (int j = 0; j < 8; j++) {
            int c = lane + 32 * j;
            float y = v[j] * sc * g0[c];
            y = y / (1.0f + expf(-y));
            s2 += y * y;
            tokA[(size_t)m * 4096 + 3840 + c] = y;
        }
#pragma unroll
        for (int o = 16; o > 0; o >>= 1) s2 += __shfl_xor_sync(0xffffffffu, s2, o);
        if (lane == 0) {
            int mm = m * 16 + 15;
            part0[mm] = s2;
            part0[M_BIG + mm] = 0.f;
            part0[2 * M_BIG + mm] = 0.f;
            part0[3 * M_BIG + mm] = 0.f;
        }
    }
}

// ---------------- launch ----------------
extern "C" void kernel_launch(void* const* d_in, const int* in_sizes, int n_in,
                              void* d_out, int out_size)
{
    const float* stoch      = (const float*)d_in[0];
    const float* deter      = (const float*)d_in[1];
    const float* action     = (const float*)d_in[2];
    const float* W0         = (const float*)d_in[3];
    const float* b0         = (const float*)d_in[4];
    const float* g0         = (const float*)d_in[5];
    const float* norm_w     = (const float*)d_in[6];
    const float* W_in       = (const float*)d_in[7];
    const float* b_in       = (const float*)d_in[8];
    const float* W_out      = (const float*)d_in[9];
    const float* b_out      = (const float*)d_in[10];
    const float* W_skip     = (const float*)d_in[11];
    const float* b_skip     = (const float*)d_in[12];
    const float* log_decay  = (const float*)d_in[13];
    const float* out_norm_w = (const float*)d_in[14];
    float* out = (float*)d_out;

    float *tokA, *tokB, *states, *cat, *part, *Wi_s, *Wo_s, *Ws_s;
    cudaGetSymbolAddress((void**)&tokA,   g_tokA);
    cudaGetSymbolAddress((void**)&tokB,   g_tokB);
    cudaGetSymbolAddress((void**)&states, g_states);
    cudaGetSymbolAddress((void**)&cat,    g_cat);
    cudaGetSymbolAddress((void**)&part,   g_part);
    cudaGetSymbolAddress((void**)&Wi_s,   g_Wi);
    cudaGetSymbolAddress((void**)&Wo_s,   g_Wo);
    cudaGetSymbolAddress((void**)&Ws_s,   g_Ws);

    cudaFuncSetAttribute(k_proj,      cudaFuncAttributeMaxDynamicSharedMemorySize, SMP_TOT);
    cudaFuncSetAttribute(k_gemm_scan, cudaFuncAttributeMaxDynamicSharedMemorySize, SM1_TOT);
    cudaFuncSetAttribute(k_gemm2,     cudaFuncAttributeMaxDynamicSharedMemorySize, SM2_TOT);

    prep_weights<<<(D_ * KIN_ + 255) / 256 + 1, 256>>>(W_in, W_out, W_skip, norm_w, W0);
    shift_scale_kernel<<<B_ * 15 / 8, 256>>>(deter, tokA, part);
    concat_kernel<<<(B_ * KIN_ + 255) / 256, 256>>>(stoch, action, cat);
    k_proj<<<B_ / 32, 256, SMP_TOT>>>(cat, b0, g0, tokA, part);

    float* Pb = tokA;
    float* Qb = tokB;
    for (int l = 0; l < L_; l++) {
        const float* Wi  = Wi_s + (size_t)l * D_ * D_;
        const float* Wo  = Wo_s + (size_t)l * D_ * D_;
        const float* Ws  = Ws_s + (size_t)l * D_ * D_;
        const float* bi  = b_in      + (size_t)l * D_;
        const float* bo  = b_out     + (size_t)l * D_;
        const float* bsk = b_skip    + (size_t)l * D_;
        const float* ld  = log_decay + (size_t)l * D_;
        float* partIn  = part + (size_t)(l & 1) * 4 * M_BIG;
        float* partOut = part + (size_t)((l + 1) & 1) * 4 * M_BIG;

        k_gemm_scan<<<dim3(74, 2), 512, SM1_TOT>>>(Pb, Wi, bi, ld, partIn, states);
        k_gemm2<<<dim3(37, 4), 512, SM2_TOT>>>(Pb, Ws, states, Wo, partIn,
                                               bo, bsk, Qb, partOut);
        float* tmp = Pb; Pb = Qb; Qb = tmp;
    }

    apply_norm_kernel<<<M_BIG / 8, 256>>>(Pb, out_norm_w, out);
}